// round 1
// baseline (speedup 1.0000x reference)
#include <cuda_runtime.h>
#include <cstdint>

#define NN 100000
#define NE 1600000
#define HH 64
#define NLAYERS 3

// ---------------- device scratch (no allocations allowed) ----------------
__device__ float4 g_h4[NN * 16];     // h: (N, 64) as float4[N*16]
__device__ float4 g_agg4[NN * 16];   // agg: (N, 64)
__device__ float  g_dx[NN * 3];      // coordinate deltas
__device__ float4 g_tmean4[16];      // mean time embedding (64)

// ---------------- small helpers ----------------
__device__ __forceinline__ float siluf(float v) {
    return __fdividef(v, 1.0f + __expf(-v));
}
__device__ __forceinline__ unsigned long long dup2(float v) {
    unsigned long long r;
    asm("mov.b64 %0, {%1, %1};" : "=l"(r) : "f"(v));
    return r;
}
__device__ __forceinline__ void ffma2(unsigned long long &d, unsigned long long a,
                                      unsigned long long b) {
    asm("fma.rn.f32x2 %0, %1, %2, %0;" : "+l"(d) : "l"(a), "l"(b));
}
__device__ __forceinline__ float2 unpack2(unsigned long long a) {
    float2 r;
    asm("mov.b64 {%0, %1}, %2;" : "=f"(r.x), "=f"(r.y) : "l"(a));
    return r;
}
__device__ __forceinline__ void red4(float *p, float a, float b, float c, float d) {
    asm volatile("red.global.add.v4.f32 [%0], {%1,%2,%3,%4};" ::"l"(p), "f"(a),
                 "f"(b), "f"(c), "f"(d)
                 : "memory");
}

// acc[k] holds output columns (2k, 2k+1) packed as f32x2.
// wrow = 64 consecutive weights W[i][0..63] in shared; v = input value ef[i].
__device__ __forceinline__ void row_fma(unsigned long long *acc,
                                        const float *wrow, float v) {
    unsigned long long vv = dup2(v);
    const ulonglong2 *w = (const ulonglong2 *)wrow;
#pragma unroll
    for (int j = 0; j < 16; j++) {
        ulonglong2 wq = w[j];       // broadcast LDS.128: 4 weights / 1 phase
        ffma2(acc[2 * j], wq.x, vv);
        ffma2(acc[2 * j + 1], wq.y, vv);
    }
}

__device__ __forceinline__ void cp_s(float *dst, const float *__restrict__ src,
                                     int nfloats, int tid, int nthr) {
    const float4 *s4 = (const float4 *)src;
    float4 *d4 = (float4 *)dst;
    for (int k = tid; k < (nfloats >> 2); k += nthr) d4[k] = s4[k];
}

// ---------------- time-embedding mean ----------------
__global__ void tmean_kernel(const float *__restrict__ t,
                             const float *__restrict__ w1,
                             const float *__restrict__ b1,
                             const float *__restrict__ w2,
                             const float *__restrict__ b2) {
    __shared__ float sS[16 * 64];
    int j = threadIdx.x;  // 0..63
    float w1j = w1[j], b1j = b1[j];
    for (int b = 0; b < 16; b++) sS[b * 64 + j] = siluf(t[b] * w1j + b1j);
    __syncthreads();
    float accm = 0.f;
    for (int b = 0; b < 16; b++) {
        float s = b2[j];
        for (int k = 0; k < 64; k++) s += sS[b * 64 + k] * w2[k * 64 + j];
        accm += s;
    }
    ((float *)g_tmean4)[j] = accm * (1.0f / 16.0f);
}

// ---------------- init: h = emb[z] + tmean, zero agg/dx, out = x ----------------
__global__ void init_kernel(const float *__restrict__ x, const int *__restrict__ z,
                            const float *__restrict__ emb, float *__restrict__ out) {
    int tid = blockIdx.x * blockDim.x + threadIdx.x;
    int stride = gridDim.x * blockDim.x;
    const float4 *emb4 = (const float4 *)emb;
    for (int idx = tid; idx < NN * 16; idx += stride) {
        int i = idx >> 4, q = idx & 15;
        float4 e = emb4[z[i] * 16 + q];
        float4 tm = g_tmean4[q];
        float4 r;
        r.x = e.x + tm.x; r.y = e.y + tm.y; r.z = e.z + tm.z; r.w = e.w + tm.w;
        g_h4[idx] = r;
        g_agg4[idx] = make_float4(0.f, 0.f, 0.f, 0.f);
    }
    for (int idx = tid; idx < NN * 3; idx += stride) {
        out[idx] = x[idx];
        g_dx[idx] = 0.f;
    }
}

// ---------------- edge kernel ----------------
// shared layout (floats)
#define E_SM_W1 0
#define E_SM_B1 8256
#define E_SM_W2 8320
#define E_SM_B2 12416
#define E_SM_C1 12480
#define E_SM_CB1 16576
#define E_SM_C2 16640
#define E_SM_CB2 16704
#define E_SM_M 16708
#define EDGE_SMEM_FLOATS (16708 + 4 * 64 * 32)
#define EDGE_SMEM_BYTES (EDGE_SMEM_FLOATS * 4)

__global__ void __launch_bounds__(128)
edge_kernel(const float *__restrict__ xin, const int *__restrict__ ei,
            const float *__restrict__ W1, const float *__restrict__ B1,
            const float *__restrict__ W2, const float *__restrict__ B2,
            const float *__restrict__ C1, const float *__restrict__ Cb1,
            const float *__restrict__ C2, const float *__restrict__ Cb2) {
    extern __shared__ float sm[];
    int tid = threadIdx.x;
    cp_s(sm + E_SM_W1, W1, 8256, tid, 128);
    cp_s(sm + E_SM_B1, B1, 64, tid, 128);
    cp_s(sm + E_SM_W2, W2, 4096, tid, 128);
    cp_s(sm + E_SM_B2, B2, 64, tid, 128);
    cp_s(sm + E_SM_C1, C1, 4096, tid, 128);
    cp_s(sm + E_SM_CB1, Cb1, 64, tid, 128);
    cp_s(sm + E_SM_C2, C2, 64, tid, 128);
    if (tid == 0) sm[E_SM_CB2] = Cb2[0];
    __syncthreads();

    const float *gh = (const float *)g_h4;
    float *gagg = (float *)g_agg4;
    int lane = tid & 31, wid = tid >> 5;
    float *sMcol = sm + E_SM_M + wid * 2048 + lane;  // private column, stride 32
    int stride = gridDim.x * blockDim.x;

    for (int e = blockIdx.x * blockDim.x + tid; e < NE; e += stride) {
        int s = ei[e];
        int d = ei[NE + e];
        float ax = xin[3 * d + 0] - xin[3 * s + 0];
        float ay = xin[3 * d + 1] - xin[3 * s + 1];
        float az = xin[3 * d + 2] - xin[3 * s + 2];
        float d2 = ax * ax + ay * ay + az * az;

        unsigned long long acc[32];
#pragma unroll
        for (int j = 0; j < 32; j++) acc[j] = 0ull;

        // GEMM1: ef = [h[d], h[s], d2] @ W1(129x64)
        const float4 *hd = (const float4 *)(gh + (size_t)d * HH);
        const float4 *hs = (const float4 *)(gh + (size_t)s * HH);
#pragma unroll 1
        for (int i4 = 0; i4 < 16; i4++) {
            float4 f = hd[i4];
            const float *wr = sm + E_SM_W1 + i4 * 256;
            row_fma(acc, wr, f.x);
            row_fma(acc, wr + 64, f.y);
            row_fma(acc, wr + 128, f.z);
            row_fma(acc, wr + 192, f.w);
        }
#pragma unroll 1
        for (int i4 = 0; i4 < 16; i4++) {
            float4 f = hs[i4];
            const float *wr = sm + E_SM_W1 + 4096 + i4 * 256;
            row_fma(acc, wr, f.x);
            row_fma(acc, wr + 64, f.y);
            row_fma(acc, wr + 128, f.z);
            row_fma(acc, wr + 192, f.w);
        }
        row_fma(acc, sm + E_SM_W1 + 8192, d2);

        // bias + silu -> m1 into private shared column
#pragma unroll
        for (int j = 0; j < 32; j++) {
            float2 a = unpack2(acc[j]);
            float2 b = *(const float2 *)(sm + E_SM_B1 + 2 * j);
            sMcol[(2 * j) * 32] = siluf(a.x + b.x);
            sMcol[(2 * j + 1) * 32] = siluf(a.y + b.y);
        }

        // GEMM2: m1 @ W2(64x64)
#pragma unroll
        for (int j = 0; j < 32; j++) acc[j] = 0ull;
#pragma unroll 1
        for (int i = 0; i < 64; i++) {
            float v = sMcol[i * 32];
            row_fma(acc, sm + E_SM_W2 + i * 64, v);
        }

        // bias + silu -> m; scatter-add agg; keep m for coord MLP
        float *aggRow = gagg + (size_t)d * HH;
#pragma unroll
        for (int q = 0; q < 16; q++) {
            float2 a0 = unpack2(acc[2 * q]);
            float2 a1 = unpack2(acc[2 * q + 1]);
            const float *bb = sm + E_SM_B2 + 4 * q;
            float m0 = siluf(a0.x + bb[0]);
            float m1 = siluf(a0.y + bb[1]);
            float m2 = siluf(a1.x + bb[2]);
            float m3 = siluf(a1.y + bb[3]);
            sMcol[(4 * q + 0) * 32] = m0;
            sMcol[(4 * q + 1) * 32] = m1;
            sMcol[(4 * q + 2) * 32] = m2;
            sMcol[(4 * q + 3) * 32] = m3;
            red4(aggRow + 4 * q, m0, m1, m2, m3);
        }

        // coord MLP: silu(m @ C1) @ C2 + cb2
#pragma unroll
        for (int j = 0; j < 32; j++) acc[j] = 0ull;
#pragma unroll 1
        for (int i = 0; i < 64; i++) {
            float v = sMcol[i * 32];
            row_fma(acc, sm + E_SM_C1 + i * 64, v);
        }
        float cw = sm[E_SM_CB2];
#pragma unroll
        for (int j = 0; j < 32; j++) {
            float2 a = unpack2(acc[j]);
            const float *bb = sm + E_SM_CB1 + 2 * j;
            const float *ww = sm + E_SM_C2 + 2 * j;
            cw += siluf(a.x + bb[0]) * ww[0] + siluf(a.y + bb[1]) * ww[1];
        }
        atomicAdd(&g_dx[3 * d + 0], ax * cw);
        atomicAdd(&g_dx[3 * d + 1], ay * cw);
        atomicAdd(&g_dx[3 * d + 2], az * cw);
    }
}

// ---------------- node kernel ----------------
#define N_SM_W1 0
#define N_SM_B1 8192
#define N_SM_W2 8256
#define N_SM_B2 12352
#define N_SM_M 12416
#define NODE_SMEM_FLOATS (12416 + 4 * 64 * 32)
#define NODE_SMEM_BYTES (NODE_SMEM_FLOATS * 4)

__global__ void __launch_bounds__(128)
node_kernel(float *__restrict__ xout, const float *__restrict__ W1,
            const float *__restrict__ B1, const float *__restrict__ W2,
            const float *__restrict__ B2) {
    extern __shared__ float sm[];
    int tid = threadIdx.x;
    cp_s(sm + N_SM_W1, W1, 8192, tid, 128);
    cp_s(sm + N_SM_B1, B1, 64, tid, 128);
    cp_s(sm + N_SM_W2, W2, 4096, tid, 128);
    cp_s(sm + N_SM_B2, B2, 64, tid, 128);
    __syncthreads();

    float *gh = (float *)g_h4;
    float *gagg = (float *)g_agg4;
    int lane = tid & 31, wid = tid >> 5;
    float *sMcol = sm + N_SM_M + wid * 2048 + lane;
    int stride = gridDim.x * blockDim.x;

    for (int i = blockIdx.x * blockDim.x + tid; i < NN; i += stride) {
        unsigned long long acc[32];
#pragma unroll
        for (int j = 0; j < 32; j++) acc[j] = 0ull;

        // nf = [h, agg] @ n_w1(128x64); agg row zeroed after read
        const float4 *hp = (const float4 *)(gh + (size_t)i * HH);
#pragma unroll 1
        for (int i4 = 0; i4 < 16; i4++) {
            float4 f = hp[i4];
            const float *wr = sm + N_SM_W1 + i4 * 256;
            row_fma(acc, wr, f.x);
            row_fma(acc, wr + 64, f.y);
            row_fma(acc, wr + 128, f.z);
            row_fma(acc, wr + 192, f.w);
        }
        float4 *ap = (float4 *)(gagg + (size_t)i * HH);
#pragma unroll 1
        for (int i4 = 0; i4 < 16; i4++) {
            float4 f = ap[i4];
            ap[i4] = make_float4(0.f, 0.f, 0.f, 0.f);  // reset for next layer
            const float *wr = sm + N_SM_W1 + 4096 + i4 * 256;
            row_fma(acc, wr, f.x);
            row_fma(acc, wr + 64, f.y);
            row_fma(acc, wr + 128, f.z);
            row_fma(acc, wr + 192, f.w);
        }
#pragma unroll
        for (int j = 0; j < 32; j++) {
            float2 a = unpack2(acc[j]);
            float2 b = *(const float2 *)(sm + N_SM_B1 + 2 * j);
            sMcol[(2 * j) * 32] = siluf(a.x + b.x);
            sMcol[(2 * j + 1) * 32] = siluf(a.y + b.y);
        }
#pragma unroll
        for (int j = 0; j < 32; j++) acc[j] = 0ull;
#pragma unroll 1
        for (int i2 = 0; i2 < 64; i2++) {
            float v = sMcol[i2 * 32];
            row_fma(acc, sm + N_SM_W2 + i2 * 64, v);
        }
        // h += acc + b2 (no final activation)
        float2 *hrow = (float2 *)(gh + (size_t)i * HH);
#pragma unroll
        for (int j = 0; j < 32; j++) {
            float2 a = unpack2(acc[j]);
            float2 b = *(const float2 *)(sm + N_SM_B2 + 2 * j);
            float2 hv = hrow[j];
            hv.x += a.x + b.x;
            hv.y += a.y + b.y;
            hrow[j] = hv;
        }
        // x += dx; reset dx
#pragma unroll
        for (int k = 0; k < 3; k++) {
            xout[3 * i + k] += g_dx[3 * i + k];
            g_dx[3 * i + k] = 0.f;
        }
    }
}

// ---------------- launch ----------------
extern "C" void kernel_launch(void *const *d_in, const int *in_sizes, int n_in,
                              void *d_out, int out_size) {
    const float *x   = (const float *)d_in[0];
    const int   *z   = (const int *)d_in[1];
    const float *t   = (const float *)d_in[2];
    const int   *ei  = (const int *)d_in[3];
    const float *emb = (const float *)d_in[4];
    const float *tw1 = (const float *)d_in[5];
    const float *tb1 = (const float *)d_in[6];
    const float *tw2 = (const float *)d_in[7];
    const float *tb2 = (const float *)d_in[8];
    const float *ew1 = (const float *)d_in[9];
    const float *eb1 = (const float *)d_in[10];
    const float *ew2 = (const float *)d_in[11];
    const float *eb2 = (const float *)d_in[12];
    const float *cw1 = (const float *)d_in[13];
    const float *cb1 = (const float *)d_in[14];
    const float *cw2 = (const float *)d_in[15];
    const float *cb2 = (const float *)d_in[16];
    const float *nw1 = (const float *)d_in[17];
    const float *nb1 = (const float *)d_in[18];
    const float *nw2 = (const float *)d_in[19];
    const float *nb2 = (const float *)d_in[20];
    float *out = (float *)d_out;

    cudaFuncSetAttribute(edge_kernel, cudaFuncAttributeMaxDynamicSharedMemorySize,
                         EDGE_SMEM_BYTES);
    cudaFuncSetAttribute(node_kernel, cudaFuncAttributeMaxDynamicSharedMemorySize,
                         NODE_SMEM_BYTES);

    tmean_kernel<<<1, 64>>>(t, tw1, tb1, tw2, tb2);
    init_kernel<<<2048, 256>>>(x, z, emb, out);
    for (int l = 0; l < NLAYERS; l++) {
        edge_kernel<<<304, 128, EDGE_SMEM_BYTES>>>(
            out, ei, ew1 + l * 8256, eb1 + l * 64, ew2 + l * 4096, eb2 + l * 64,
            cw1 + l * 4096, cb1 + l * 64, cw2 + l * 64, cb2 + l);
        node_kernel<<<304, 128, NODE_SMEM_BYTES>>>(
            out, nw1 + l * 8192, nb1 + l * 64, nw2 + l * 4096, nb2 + l * 64);
    }
    (void)in_sizes; (void)n_in; (void)out_size;
}

// round 2
// speedup vs baseline: 1.4399x; 1.4399x over previous
#include <cuda_runtime.h>
#include <cstdint>

#define NN 100000
#define NE 1600000
#define HH 64
#define NLAYERS 3

// ---------------- device scratch (no allocations allowed) ----------------
__device__ float4 g_h4[NN * 16];     // h: (N, 64)
__device__ float4 g_agg4[NN * 16];   // agg: (N, 64)
__device__ float4 g_a4[NN * 16];     // a[n] = h[n] @ W1[0:64] + b1   (dst side)
__device__ float4 g_b4[NN * 16];     // b[n] = h[n] @ W1[64:128]      (src side)
__device__ float  g_dx[NN * 3];      // coordinate deltas
__device__ float4 g_tmean4[16];      // mean time embedding (64)

// ---------------- small helpers ----------------
__device__ __forceinline__ float siluf(float v) {
    return __fdividef(v, 1.0f + __expf(-v));
}
__device__ __forceinline__ unsigned long long dup2(float v) {
    unsigned long long r;
    asm("mov.b64 %0, {%1, %1};" : "=l"(r) : "f"(v));
    return r;
}
__device__ __forceinline__ void ffma2(unsigned long long &d, unsigned long long a,
                                      unsigned long long b) {
    asm("fma.rn.f32x2 %0, %1, %2, %0;" : "+l"(d) : "l"(a), "l"(b));
}
__device__ __forceinline__ float2 unpack2(unsigned long long a) {
    float2 r;
    asm("mov.b64 {%0, %1}, %2;" : "=f"(r.x), "=f"(r.y) : "l"(a));
    return r;
}
__device__ __forceinline__ void red4(float *p, float a, float b, float c, float d) {
    asm volatile("red.global.add.v4.f32 [%0], {%1,%2,%3,%4};" ::"l"(p), "f"(a),
                 "f"(b), "f"(c), "f"(d)
                 : "memory");
}

// acc[k] holds output columns (2k, 2k+1) packed as f32x2.
__device__ __forceinline__ void row_fma(unsigned long long *acc,
                                        const float *wrow, float v) {
    unsigned long long vv = dup2(v);
    const ulonglong2 *w = (const ulonglong2 *)wrow;
#pragma unroll
    for (int j = 0; j < 16; j++) {
        ulonglong2 wq = w[j];  // broadcast LDS.128
        ffma2(acc[2 * j], wq.x, vv);
        ffma2(acc[2 * j + 1], wq.y, vv);
    }
}

__device__ __forceinline__ void cp_s(float *dst, const float *__restrict__ src,
                                     int nfloats, int tid, int nthr) {
    const float4 *s4 = (const float4 *)src;
    float4 *d4 = (float4 *)dst;
    for (int k = tid; k < (nfloats >> 2); k += nthr) d4[k] = s4[k];
}

// ---------------- time-embedding mean ----------------
__global__ void tmean_kernel(const float *__restrict__ t,
                             const float *__restrict__ w1,
                             const float *__restrict__ b1,
                             const float *__restrict__ w2,
                             const float *__restrict__ b2) {
    __shared__ float sS[16 * 64];
    int j = threadIdx.x;  // 0..63
    float w1j = w1[j], b1j = b1[j];
    for (int b = 0; b < 16; b++) sS[b * 64 + j] = siluf(t[b] * w1j + b1j);
    __syncthreads();
    float accm = 0.f;
    for (int b = 0; b < 16; b++) {
        float s = b2[j];
        for (int k = 0; k < 64; k++) s += sS[b * 64 + k] * w2[k * 64 + j];
        accm += s;
    }
    ((float *)g_tmean4)[j] = accm * (1.0f / 16.0f);
}

// ---------------- init: h = emb[z] + tmean, zero agg/dx, out = x ----------------
__global__ void init_kernel(const float *__restrict__ x, const int *__restrict__ z,
                            const float *__restrict__ emb, float *__restrict__ out) {
    int tid = blockIdx.x * blockDim.x + threadIdx.x;
    int stride = gridDim.x * blockDim.x;
    const float4 *emb4 = (const float4 *)emb;
    for (int idx = tid; idx < NN * 16; idx += stride) {
        int i = idx >> 4, q = idx & 15;
        float4 e = emb4[z[i] * 16 + q];
        float4 tm = g_tmean4[q];
        float4 r;
        r.x = e.x + tm.x; r.y = e.y + tm.y; r.z = e.z + tm.z; r.w = e.w + tm.w;
        g_h4[idx] = r;
        g_agg4[idx] = make_float4(0.f, 0.f, 0.f, 0.f);
    }
    for (int idx = tid; idx < NN * 3; idx += stride) {
        out[idx] = x[idx];
        g_dx[idx] = 0.f;
    }
}

// ---------------- precompute kernel: a[n], b[n] from h[n] ----------------
// smem: W1a (4096), W1b (4096), b1 (64)
#define P_SM_W1A 0
#define P_SM_W1B 4096
#define P_SM_B1 8192
#define PRE_SMEM_BYTES ((8192 + 64) * 4)

__global__ void __launch_bounds__(128, 3)
pre_kernel(const float *__restrict__ W1, const float *__restrict__ B1) {
    extern __shared__ float sm[];
    int tid = threadIdx.x;
    cp_s(sm + P_SM_W1A, W1, 8192, tid, 128);  // rows 0..127 of W1 (129x64)
    cp_s(sm + P_SM_B1, B1, 64, tid, 128);
    __syncthreads();

    const float *gh = (const float *)g_h4;
    int stride = gridDim.x * blockDim.x;
    for (int i = blockIdx.x * blockDim.x + tid; i < NN; i += stride) {
        unsigned long long accA[32], accB[32];
#pragma unroll
        for (int j = 0; j < 32; j++) { accA[j] = 0ull; accB[j] = 0ull; }
        const float4 *hp = (const float4 *)(gh + (size_t)i * HH);
#pragma unroll 1
        for (int q = 0; q < 16; q++) {
            float4 f = hp[q];
            const float *wa = sm + P_SM_W1A + q * 256;
            const float *wb = sm + P_SM_W1B + q * 256;
            row_fma(accA, wa, f.x);       row_fma(accB, wb, f.x);
            row_fma(accA, wa + 64, f.y);  row_fma(accB, wb + 64, f.y);
            row_fma(accA, wa + 128, f.z); row_fma(accB, wb + 128, f.z);
            row_fma(accA, wa + 192, f.w); row_fma(accB, wb + 192, f.w);
        }
        float2 *ap = (float2 *)((float *)g_a4 + (size_t)i * HH);
        float2 *bp = (float2 *)((float *)g_b4 + (size_t)i * HH);
#pragma unroll
        for (int j = 0; j < 32; j++) {
            float2 va = unpack2(accA[j]);
            float2 bb = *(const float2 *)(sm + P_SM_B1 + 2 * j);
            va.x += bb.x; va.y += bb.y;
            ap[j] = va;
            float2 vb = unpack2(accB[j]);
            bp[j] = vb;
        }
    }
}

// ---------------- edge kernel ----------------
// smem floats:
#define E_SM_W129 0
#define E_SM_W2 64
#define E_SM_B2 4160
#define E_SM_C1 4224
#define E_SM_CB1 8320
#define E_SM_C2 8384
#define E_SM_CB2 8448
#define E_SM_M 8464
#define EDGE_SMEM_FLOATS (8464 + 4 * 2048)
#define EDGE_SMEM_BYTES (EDGE_SMEM_FLOATS * 4)

__global__ void __launch_bounds__(128, 3)
edge_kernel(const float *__restrict__ xin, const int *__restrict__ ei,
            const float *__restrict__ W1, const float *__restrict__ W2,
            const float *__restrict__ B2, const float *__restrict__ C1,
            const float *__restrict__ Cb1, const float *__restrict__ C2,
            const float *__restrict__ Cb2) {
    extern __shared__ float sm[];
    int tid = threadIdx.x;
    cp_s(sm + E_SM_W129, W1 + 8192, 64, tid, 128);  // last row of W1 (d2 weights)
    cp_s(sm + E_SM_W2, W2, 4096, tid, 128);
    cp_s(sm + E_SM_B2, B2, 64, tid, 128);
    cp_s(sm + E_SM_C1, C1, 4096, tid, 128);
    cp_s(sm + E_SM_CB1, Cb1, 64, tid, 128);
    cp_s(sm + E_SM_C2, C2, 64, tid, 128);
    if (tid == 0) sm[E_SM_CB2] = Cb2[0];
    __syncthreads();

    const float *ga = (const float *)g_a4;
    const float *gb = (const float *)g_b4;
    float *gagg = (float *)g_agg4;
    int lane = tid & 31, wid = tid >> 5;
    float *sMcol = sm + E_SM_M + wid * 2048 + lane;  // private column, stride 32
    int stride = gridDim.x * blockDim.x;

    for (int e = blockIdx.x * blockDim.x + tid; e < NE; e += stride) {
        int s = ei[e];
        int d = ei[NE + e];
        float ax = xin[3 * d + 0] - xin[3 * s + 0];
        float ay = xin[3 * d + 1] - xin[3 * s + 1];
        float az = xin[3 * d + 2] - xin[3 * s + 2];
        float d2 = ax * ax + ay * ay + az * az;

        // ef = a[d] + b[s] + d2 * w129; m1 = silu(ef) -> staged
        const float4 *A4 = (const float4 *)(ga + (size_t)d * HH);
        const float4 *B4 = (const float4 *)(gb + (size_t)s * HH);
        const float4 *w129 = (const float4 *)(sm + E_SM_W129);
#pragma unroll
        for (int q = 0; q < 16; q++) {
            float4 av = A4[q];
            float4 bv = B4[q];
            float4 wv = w129[q];
            sMcol[(4 * q + 0) * 32] = siluf(fmaf(d2, wv.x, av.x + bv.x));
            sMcol[(4 * q + 1) * 32] = siluf(fmaf(d2, wv.y, av.y + bv.y));
            sMcol[(4 * q + 2) * 32] = siluf(fmaf(d2, wv.z, av.z + bv.z));
            sMcol[(4 * q + 3) * 32] = siluf(fmaf(d2, wv.w, av.w + bv.w));
        }

        // GEMM2: m1 @ W2 (64x64)
        unsigned long long acc[32];
#pragma unroll
        for (int j = 0; j < 32; j++) acc[j] = 0ull;
#pragma unroll 4
        for (int i = 0; i < 64; i++) {
            float v = sMcol[i * 32];
            row_fma(acc, sm + E_SM_W2 + i * 64, v);
        }

        // bias + silu -> m; scatter-add agg; re-stage for coord MLP
        float *aggRow = gagg + (size_t)d * HH;
#pragma unroll
        for (int q = 0; q < 16; q++) {
            float2 a0 = unpack2(acc[2 * q]);
            float2 a1 = unpack2(acc[2 * q + 1]);
            const float *bb = sm + E_SM_B2 + 4 * q;
            float m0 = siluf(a0.x + bb[0]);
            float m1 = siluf(a0.y + bb[1]);
            float m2 = siluf(a1.x + bb[2]);
            float m3 = siluf(a1.y + bb[3]);
            sMcol[(4 * q + 0) * 32] = m0;
            sMcol[(4 * q + 1) * 32] = m1;
            sMcol[(4 * q + 2) * 32] = m2;
            sMcol[(4 * q + 3) * 32] = m3;
            red4(aggRow + 4 * q, m0, m1, m2, m3);
        }

        // coord MLP: cw = silu(m @ C1 + cb1) @ C2 + cb2
#pragma unroll
        for (int j = 0; j < 32; j++) acc[j] = 0ull;
#pragma unroll 4
        for (int i = 0; i < 64; i++) {
            float v = sMcol[i * 32];
            row_fma(acc, sm + E_SM_C1 + i * 64, v);
        }
        float cw = sm[E_SM_CB2];
#pragma unroll
        for (int j = 0; j < 32; j++) {
            float2 a = unpack2(acc[j]);
            float2 bb = *(const float2 *)(sm + E_SM_CB1 + 2 * j);
            float2 ww = *(const float2 *)(sm + E_SM_C2 + 2 * j);
            cw += siluf(a.x + bb.x) * ww.x + siluf(a.y + bb.y) * ww.y;
        }
        atomicAdd(&g_dx[3 * d + 0], ax * cw);
        atomicAdd(&g_dx[3 * d + 1], ay * cw);
        atomicAdd(&g_dx[3 * d + 2], az * cw);
    }
}

// ---------------- node kernel (register-resident m, no smem scratch) ----------------
#define N_SM_W1 0
#define N_SM_B1 8192
#define N_SM_W2 8256
#define N_SM_B2 12352
#define NODE_SMEM_BYTES (12416 * 4)

__global__ void __launch_bounds__(128, 3)
node_kernel(float *__restrict__ xout, const float *__restrict__ W1,
            const float *__restrict__ B1, const float *__restrict__ W2,
            const float *__restrict__ B2) {
    extern __shared__ float sm[];
    int tid = threadIdx.x;
    cp_s(sm + N_SM_W1, W1, 8192, tid, 128);
    cp_s(sm + N_SM_B1, B1, 64, tid, 128);
    cp_s(sm + N_SM_W2, W2, 4096, tid, 128);
    cp_s(sm + N_SM_B2, B2, 64, tid, 128);
    __syncthreads();

    float *gh = (float *)g_h4;
    float *gagg = (float *)g_agg4;
    int stride = gridDim.x * blockDim.x;

    for (int i = blockIdx.x * blockDim.x + tid; i < NN; i += stride) {
        unsigned long long acc[32];
#pragma unroll
        for (int j = 0; j < 32; j++) acc[j] = 0ull;

        // nf = [h, agg] @ n_w1(128x64); agg row zeroed after read
        const float4 *hp = (const float4 *)(gh + (size_t)i * HH);
#pragma unroll 1
        for (int i4 = 0; i4 < 16; i4++) {
            float4 f = hp[i4];
            const float *wr = sm + N_SM_W1 + i4 * 256;
            row_fma(acc, wr, f.x);
            row_fma(acc, wr + 64, f.y);
            row_fma(acc, wr + 128, f.z);
            row_fma(acc, wr + 192, f.w);
        }
        float4 *ap = (float4 *)(gagg + (size_t)i * HH);
#pragma unroll 1
        for (int i4 = 0; i4 < 16; i4++) {
            float4 f = ap[i4];
            ap[i4] = make_float4(0.f, 0.f, 0.f, 0.f);  // reset for next layer
            const float *wr = sm + N_SM_W1 + 4096 + i4 * 256;
            row_fma(acc, wr, f.x);
            row_fma(acc, wr + 64, f.y);
            row_fma(acc, wr + 128, f.z);
            row_fma(acc, wr + 192, f.w);
        }
        // m1 = silu(acc + b1) kept in registers
        float m[64];
#pragma unroll
        for (int j = 0; j < 32; j++) {
            float2 a = unpack2(acc[j]);
            float2 b = *(const float2 *)(sm + N_SM_B1 + 2 * j);
            m[2 * j] = siluf(a.x + b.x);
            m[2 * j + 1] = siluf(a.y + b.y);
        }
#pragma unroll
        for (int j = 0; j < 32; j++) acc[j] = 0ull;
#pragma unroll
        for (int i2 = 0; i2 < 64; i2++) {
            row_fma(acc, sm + N_SM_W2 + i2 * 64, m[i2]);
        }
        // h += acc + b2 (no final activation)
        float2 *hrow = (float2 *)(gh + (size_t)i * HH);
#pragma unroll
        for (int j = 0; j < 32; j++) {
            float2 a = unpack2(acc[j]);
            float2 b = *(const float2 *)(sm + N_SM_B2 + 2 * j);
            float2 hv = hrow[j];
            hv.x += a.x + b.x;
            hv.y += a.y + b.y;
            hrow[j] = hv;
        }
        // x += dx; reset dx
#pragma unroll
        for (int k = 0; k < 3; k++) {
            xout[3 * i + k] += g_dx[3 * i + k];
            g_dx[3 * i + k] = 0.f;
        }
    }
}

// ---------------- launch ----------------
extern "C" void kernel_launch(void *const *d_in, const int *in_sizes, int n_in,
                              void *d_out, int out_size) {
    const float *x   = (const float *)d_in[0];
    const int   *z   = (const int *)d_in[1];
    const float *t   = (const float *)d_in[2];
    const int   *ei  = (const int *)d_in[3];
    const float *emb = (const float *)d_in[4];
    const float *tw1 = (const float *)d_in[5];
    const float *tb1 = (const float *)d_in[6];
    const float *tw2 = (const float *)d_in[7];
    const float *tb2 = (const float *)d_in[8];
    const float *ew1 = (const float *)d_in[9];
    const float *eb1 = (const float *)d_in[10];
    const float *ew2 = (const float *)d_in[11];
    const float *eb2 = (const float *)d_in[12];
    const float *cw1 = (const float *)d_in[13];
    const float *cb1 = (const float *)d_in[14];
    const float *cw2 = (const float *)d_in[15];
    const float *cb2 = (const float *)d_in[16];
    const float *nw1 = (const float *)d_in[17];
    const float *nb1 = (const float *)d_in[18];
    const float *nw2 = (const float *)d_in[19];
    const float *nb2 = (const float *)d_in[20];
    float *out = (float *)d_out;

    cudaFuncSetAttribute(edge_kernel, cudaFuncAttributeMaxDynamicSharedMemorySize,
                         EDGE_SMEM_BYTES);
    cudaFuncSetAttribute(node_kernel, cudaFuncAttributeMaxDynamicSharedMemorySize,
                         NODE_SMEM_BYTES);
    cudaFuncSetAttribute(pre_kernel, cudaFuncAttributeMaxDynamicSharedMemorySize,
                         PRE_SMEM_BYTES);

    tmean_kernel<<<1, 64>>>(t, tw1, tb1, tw2, tb2);
    init_kernel<<<2048, 256>>>(x, z, emb, out);
    for (int l = 0; l < NLAYERS; l++) {
        pre_kernel<<<444, 128, PRE_SMEM_BYTES>>>(ew1 + l * 8256, eb1 + l * 64);
        edge_kernel<<<444, 128, EDGE_SMEM_BYTES>>>(
            out, ei, ew1 + l * 8256, ew2 + l * 4096, eb2 + l * 64,
            cw1 + l * 4096, cb1 + l * 64, cw2 + l * 64, cb2 + l);
        node_kernel<<<444, 128, NODE_SMEM_BYTES>>>(
            out, nw1 + l * 8192, nb1 + l * 64, nw2 + l * 4096, nb2 + l * 64);
    }
    (void)in_sizes; (void)n_in; (void)out_size;
}

// round 3
// speedup vs baseline: 2.7550x; 1.9134x over previous
#include <cuda_runtime.h>
#include <cstdint>

#define NN 100000
#define NE 1600000
#define HH 64
#define NLAYERS 3

// ---------------- device scratch ----------------
__device__ float4 g_h4[NN * 16];     // h: (N, 64)
__device__ float4 g_agg4[NN * 16];   // agg: (N, 64)
__device__ float4 g_a4[NN * 16];     // a[n] = h[n] @ W1[0:64] + b1   (dst side)
__device__ float4 g_b4[NN * 16];     // b[n] = h[n] @ W1[64:128]      (src side)
__device__ float  g_dx[NN * 3];
__device__ float4 g_tmean4[16];

// ---------------- helpers ----------------
__device__ __forceinline__ float siluf(float v) {
    return __fdividef(v, 1.0f + __expf(-v));
}
__device__ __forceinline__ unsigned long long dup2(float v) {
    unsigned long long r;
    asm("mov.b64 %0, {%1, %1};" : "=l"(r) : "f"(v));
    return r;
}
__device__ __forceinline__ void ffma2(unsigned long long &d, unsigned long long a,
                                      unsigned long long b) {
    asm("fma.rn.f32x2 %0, %1, %2, %0;" : "+l"(d) : "l"(a), "l"(b));
}
__device__ __forceinline__ float2 unpack2(unsigned long long a) {
    float2 r;
    asm("mov.b64 {%0, %1}, %2;" : "=f"(r.x), "=f"(r.y) : "l"(a));
    return r;
}
__device__ __forceinline__ void red2(float *p, float a, float b) {
    asm volatile("red.global.add.v2.f32 [%0], {%1,%2};" ::"l"(p), "f"(a), "f"(b)
                 : "memory");
}
__device__ __forceinline__ void red1(float *p, float a) {
    asm volatile("red.global.add.f32 [%0], %1;" ::"l"(p), "f"(a) : "memory");
}
__device__ __forceinline__ uint32_t to_tf32(float f) {
    uint32_t r;
    asm("cvt.rna.tf32.f32 %0, %1;" : "=r"(r) : "f"(f));
    return r;
}
__device__ __forceinline__ void mma_tf32(float (&d)[4], const uint32_t (&a)[4],
                                         const uint32_t (&b)[2]) {
    asm volatile(
        "mma.sync.aligned.m16n8k8.row.col.f32.tf32.tf32.f32 "
        "{%0,%1,%2,%3}, {%4,%5,%6,%7}, {%8,%9}, {%0,%1,%2,%3};\n"
        : "+f"(d[0]), "+f"(d[1]), "+f"(d[2]), "+f"(d[3])
        : "r"(a[0]), "r"(a[1]), "r"(a[2]), "r"(a[3]), "r"(b[0]), "r"(b[1]));
}

// 32x64 = (32x64 tf32 in m1s, row stride 68) @ Wt (64x64, stored transposed
// [n][k] row stride 68). acc[m][n][0..3] per m16n8k8 C layout.
__device__ __forceinline__ void gemm_32x64x64(float (&acc)[2][8][4],
                                              const uint32_t *__restrict__ m1s,
                                              const uint32_t *__restrict__ Wt,
                                              int g, int q) {
#pragma unroll
    for (int k = 0; k < 8; k++) {
        uint32_t B[8][2];
#pragma unroll
        for (int n = 0; n < 8; n++) {
            const uint32_t *bp = Wt + (8 * n + g) * 68 + 8 * k + q;
            B[n][0] = bp[0];
            B[n][1] = bp[4];
        }
#pragma unroll
        for (int m = 0; m < 2; m++) {
            const uint32_t *ap = m1s + (16 * m + g) * 68 + 8 * k + q;
            uint32_t A[4];
            A[0] = ap[0];
            A[1] = ap[8 * 68];
            A[2] = ap[4];
            A[3] = ap[8 * 68 + 4];
#pragma unroll
            for (int n = 0; n < 8; n++) mma_tf32(acc[m][n], A, B[n]);
        }
    }
}

// row_fma for SIMT aux kernels
__device__ __forceinline__ void row_fma(unsigned long long *acc,
                                        const float *wrow, float v) {
    unsigned long long vv = dup2(v);
    const ulonglong2 *w = (const ulonglong2 *)wrow;
#pragma unroll
    for (int j = 0; j < 16; j++) {
        ulonglong2 wq = w[j];
        ffma2(acc[2 * j], wq.x, vv);
        ffma2(acc[2 * j + 1], wq.y, vv);
    }
}

__device__ __forceinline__ void cp_s(float *dst, const float *__restrict__ src,
                                     int nfloats, int tid, int nthr) {
    const float4 *s4 = (const float4 *)src;
    float4 *d4 = (float4 *)dst;
    for (int k = tid; k < (nfloats >> 2); k += nthr) d4[k] = s4[k];
}

// ---------------- time-embedding mean ----------------
__global__ void tmean_kernel(const float *__restrict__ t,
                             const float *__restrict__ w1,
                             const float *__restrict__ b1,
                             const float *__restrict__ w2,
                             const float *__restrict__ b2) {
    __shared__ float sS[16 * 64];
    int j = threadIdx.x;
    float w1j = w1[j], b1j = b1[j];
    for (int b = 0; b < 16; b++) sS[b * 64 + j] = siluf(t[b] * w1j + b1j);
    __syncthreads();
    float accm = 0.f;
    for (int b = 0; b < 16; b++) {
        float s = b2[j];
        for (int k = 0; k < 64; k++) s += sS[b * 64 + k] * w2[k * 64 + j];
        accm += s;
    }
    ((float *)g_tmean4)[j] = accm * (1.0f / 16.0f);
}

// ---------------- init ----------------
__global__ void init_kernel(const float *__restrict__ x, const int *__restrict__ z,
                            const float *__restrict__ emb, float *__restrict__ out) {
    int tid = blockIdx.x * blockDim.x + threadIdx.x;
    int stride = gridDim.x * blockDim.x;
    const float4 *emb4 = (const float4 *)emb;
    for (int idx = tid; idx < NN * 16; idx += stride) {
        int i = idx >> 4, qq = idx & 15;
        float4 e = emb4[z[i] * 16 + qq];
        float4 tm = g_tmean4[qq];
        float4 r;
        r.x = e.x + tm.x; r.y = e.y + tm.y; r.z = e.z + tm.z; r.w = e.w + tm.w;
        g_h4[idx] = r;
        g_agg4[idx] = make_float4(0.f, 0.f, 0.f, 0.f);
    }
    for (int idx = tid; idx < NN * 3; idx += stride) {
        out[idx] = x[idx];
        g_dx[idx] = 0.f;
    }
}

// ---------------- pre: a[n], b[n] ----------------
#define P_SM_W1A 0
#define P_SM_W1B 4096
#define P_SM_B1 8192
#define PRE_SMEM_BYTES ((8192 + 64) * 4)

__global__ void __launch_bounds__(128, 3)
pre_kernel(const float *__restrict__ W1, const float *__restrict__ B1) {
    extern __shared__ float sm[];
    int tid = threadIdx.x;
    cp_s(sm + P_SM_W1A, W1, 8192, tid, 128);
    cp_s(sm + P_SM_B1, B1, 64, tid, 128);
    __syncthreads();

    const float *gh = (const float *)g_h4;
    int stride = gridDim.x * blockDim.x;
    for (int i = blockIdx.x * blockDim.x + tid; i < NN; i += stride) {
        unsigned long long accA[32], accB[32];
#pragma unroll
        for (int j = 0; j < 32; j++) { accA[j] = 0ull; accB[j] = 0ull; }
        const float4 *hp = (const float4 *)(gh + (size_t)i * HH);
#pragma unroll 1
        for (int qq = 0; qq < 16; qq++) {
            float4 f = hp[qq];
            const float *wa = sm + P_SM_W1A + qq * 256;
            const float *wb = sm + P_SM_W1B + qq * 256;
            row_fma(accA, wa, f.x);       row_fma(accB, wb, f.x);
            row_fma(accA, wa + 64, f.y);  row_fma(accB, wb + 64, f.y);
            row_fma(accA, wa + 128, f.z); row_fma(accB, wb + 128, f.z);
            row_fma(accA, wa + 192, f.w); row_fma(accB, wb + 192, f.w);
        }
        float2 *ap = (float2 *)((float *)g_a4 + (size_t)i * HH);
        float2 *bp = (float2 *)((float *)g_b4 + (size_t)i * HH);
#pragma unroll
        for (int j = 0; j < 32; j++) {
            float2 va = unpack2(accA[j]);
            float2 bb = *(const float2 *)(sm + P_SM_B1 + 2 * j);
            va.x += bb.x; va.y += bb.y;
            ap[j] = va;
            bp[j] = unpack2(accB[j]);
        }
    }
}

// ---------------- edge kernel (tensor core, tf32 mma.sync) ----------------
// smem words:
#define E_W2T 0
#define E_C1T 4352
#define E_B2 8704
#define E_CB1 8768
#define E_C2 8832
#define E_W129 8896
#define E_CB2 8960
#define E_WARP 8964
#define E_WARP_WORDS 2208   /* m1s 32*68 + cwbuf 32 */
#define EDGE_SMEM_WORDS (E_WARP + 4 * E_WARP_WORDS)
#define EDGE_SMEM_BYTES (EDGE_SMEM_WORDS * 4)

__global__ void __launch_bounds__(128, 3)
edge_kernel(const float *__restrict__ xin, const int *__restrict__ ei,
            const float *__restrict__ W1, const float *__restrict__ W2,
            const float *__restrict__ B2, const float *__restrict__ C1,
            const float *__restrict__ Cb1, const float *__restrict__ C2,
            const float *__restrict__ Cb2) {
    extern __shared__ float sm[];
    uint32_t *smu = (uint32_t *)sm;
    int tid = threadIdx.x;

    // stage weights: W2^T and C1^T as tf32, row stride 68
    for (int idx = tid; idx < 4096; idx += 128) {
        int kk = idx >> 6, nn = idx & 63;
        smu[E_W2T + nn * 68 + kk] = to_tf32(W2[idx]);
        smu[E_C1T + nn * 68 + kk] = to_tf32(C1[idx]);
    }
    cp_s(sm + E_B2, B2, 64, tid, 128);
    cp_s(sm + E_CB1, Cb1, 64, tid, 128);
    cp_s(sm + E_C2, C2, 64, tid, 128);
    cp_s(sm + E_W129, W1 + 8192, 64, tid, 128);
    if (tid == 0) sm[E_CB2] = Cb2[0];
    __syncthreads();

    const int lane = tid & 31;
    const int wid = tid >> 5;
    const int g = lane >> 2;   // group id
    const int q = lane & 3;    // thread in group
    uint32_t *m1s = smu + E_WARP + wid * E_WARP_WORDS;
    float *cwbuf = sm + E_WARP + wid * E_WARP_WORDS + 2176;

    const float *ga = (const float *)g_a4;
    const float *gb = (const float *)g_b4;
    float *gagg = (float *)g_agg4;

    const float w129x = sm[E_W129 + 2 * lane];
    const float w129y = sm[E_W129 + 2 * lane + 1];
    const float cb2v = sm[E_CB2];

    int gwarp = blockIdx.x * 4 + wid;
    int nwarps = gridDim.x * 4;

    for (int eb = gwarp * 32; eb < NE; eb += nwarps * 32) {
        // ---- phase 0: per-edge meta (lane = edge) ----
        int e = eb + lane;
        int s = ei[e];
        int d = ei[NE + e];
        float ax = xin[3 * d + 0] - xin[3 * s + 0];
        float ay = xin[3 * d + 1] - xin[3 * s + 1];
        float az = xin[3 * d + 2] - xin[3 * s + 2];
        float d2 = ax * ax + ay * ay + az * az;

        // ---- phase 1: m1 = silu(a[d] + b[s] + d2*w129), lane = col pair ----
#pragma unroll
        for (int t = 0; t < 32; t++) {
            int dt = __shfl_sync(0xffffffffu, d, t);
            int st = __shfl_sync(0xffffffffu, s, t);
            float d2t = __shfl_sync(0xffffffffu, d2, t);
            float2 av = *(const float2 *)(ga + (size_t)dt * HH + 2 * lane);
            float2 bv = *(const float2 *)(gb + (size_t)st * HH + 2 * lane);
            float m0 = siluf(fmaf(d2t, w129x, av.x + bv.x));
            float m1v = siluf(fmaf(d2t, w129y, av.y + bv.y));
            uint2 pk;
            pk.x = to_tf32(m0);
            pk.y = to_tf32(m1v);
            *(uint2 *)(m1s + t * 68 + 2 * lane) = pk;
        }
        __syncwarp();

        // ---- GEMM2: m = silu(m1 @ W2 + b2) ----
        float acc[2][8][4];
#pragma unroll
        for (int m = 0; m < 2; m++)
#pragma unroll
            for (int n = 0; n < 8; n++)
#pragma unroll
                for (int v = 0; v < 4; v++) acc[m][n][v] = 0.f;
        gemm_32x64x64(acc, m1s, smu + E_W2T, g, q);
        __syncwarp();

        // epilogue: silu, scatter agg (red.v2 row-coalesced), restage as tf32
#pragma unroll
        for (int m = 0; m < 2; m++) {
            int r0 = 16 * m + g;
            int r1 = r0 + 8;
            int d0 = __shfl_sync(0xffffffffu, d, r0);
            int d1 = __shfl_sync(0xffffffffu, d, r1);
            float *agg0 = gagg + (size_t)d0 * HH;
            float *agg1 = gagg + (size_t)d1 * HH;
#pragma unroll
            for (int n = 0; n < 8; n++) {
                int c0 = 8 * n + 2 * q;
                float b2x = sm[E_B2 + c0], b2y = sm[E_B2 + c0 + 1];
                float v00 = siluf(acc[m][n][0] + b2x);
                float v01 = siluf(acc[m][n][1] + b2y);
                float v10 = siluf(acc[m][n][2] + b2x);
                float v11 = siluf(acc[m][n][3] + b2y);
                red2(agg0 + c0, v00, v01);
                red2(agg1 + c0, v10, v11);
                uint2 p0, p1;
                p0.x = to_tf32(v00); p0.y = to_tf32(v01);
                p1.x = to_tf32(v10); p1.y = to_tf32(v11);
                *(uint2 *)(m1s + r0 * 68 + c0) = p0;
                *(uint2 *)(m1s + r1 * 68 + c0) = p1;
                acc[m][n][0] = 0.f; acc[m][n][1] = 0.f;
                acc[m][n][2] = 0.f; acc[m][n][3] = 0.f;
            }
        }
        __syncwarp();

        // ---- GEMM C1: c1 = silu(m @ C1 + cb1); cw = c1 @ C2 + cb2 ----
        gemm_32x64x64(acc, m1s, smu + E_C1T, g, q);

        float cwp[2][2] = {{0.f, 0.f}, {0.f, 0.f}};
#pragma unroll
        for (int m = 0; m < 2; m++)
#pragma unroll
            for (int n = 0; n < 8; n++) {
                int c0 = 8 * n + 2 * q;
                float cb1x = sm[E_CB1 + c0], cb1y = sm[E_CB1 + c0 + 1];
                float c2x = sm[E_C2 + c0], c2y = sm[E_C2 + c0 + 1];
                cwp[m][0] += siluf(acc[m][n][0] + cb1x) * c2x +
                             siluf(acc[m][n][1] + cb1y) * c2y;
                cwp[m][1] += siluf(acc[m][n][2] + cb1x) * c2x +
                             siluf(acc[m][n][3] + cb1y) * c2y;
            }
        // reduce across the 4 lanes of each quad
#pragma unroll
        for (int ofs = 1; ofs <= 2; ofs <<= 1) {
#pragma unroll
            for (int m = 0; m < 2; m++) {
                cwp[m][0] += __shfl_xor_sync(0xffffffffu, cwp[m][0], ofs);
                cwp[m][1] += __shfl_xor_sync(0xffffffffu, cwp[m][1], ofs);
            }
        }
        if (q == 0) {
#pragma unroll
            for (int m = 0; m < 2; m++) {
                cwbuf[16 * m + g] = cwp[m][0] + cb2v;
                cwbuf[16 * m + g + 8] = cwp[m][1] + cb2v;
            }
        }
        __syncwarp();

        // ---- phase 6: dx scatter (lane = edge) ----
        float cw = cwbuf[lane];
        red1(&g_dx[3 * d + 0], ax * cw);
        red1(&g_dx[3 * d + 1], ay * cw);
        red1(&g_dx[3 * d + 2], az * cw);
        __syncwarp();
    }
}

// ---------------- node kernel ----------------
#define N_SM_W1 0
#define N_SM_B1 8192
#define N_SM_W2 8256
#define N_SM_B2 12352
#define NODE_SMEM_BYTES (12416 * 4)

__global__ void __launch_bounds__(128, 3)
node_kernel(float *__restrict__ xout, const float *__restrict__ W1,
            const float *__restrict__ B1, const float *__restrict__ W2,
            const float *__restrict__ B2) {
    extern __shared__ float sm[];
    int tid = threadIdx.x;
    cp_s(sm + N_SM_W1, W1, 8192, tid, 128);
    cp_s(sm + N_SM_B1, B1, 64, tid, 128);
    cp_s(sm + N_SM_W2, W2, 4096, tid, 128);
    cp_s(sm + N_SM_B2, B2, 64, tid, 128);
    __syncthreads();

    float *gh = (float *)g_h4;
    float *gagg = (float *)g_agg4;
    int stride = gridDim.x * blockDim.x;

    for (int i = blockIdx.x * blockDim.x + tid; i < NN; i += stride) {
        unsigned long long acc[32];
#pragma unroll
        for (int j = 0; j < 32; j++) acc[j] = 0ull;

        const float4 *hp = (const float4 *)(gh + (size_t)i * HH);
#pragma unroll 1
        for (int i4 = 0; i4 < 16; i4++) {
            float4 f = hp[i4];
            const float *wr = sm + N_SM_W1 + i4 * 256;
            row_fma(acc, wr, f.x);
            row_fma(acc, wr + 64, f.y);
            row_fma(acc, wr + 128, f.z);
            row_fma(acc, wr + 192, f.w);
        }
        float4 *ap = (float4 *)(gagg + (size_t)i * HH);
#pragma unroll 1
        for (int i4 = 0; i4 < 16; i4++) {
            float4 f = ap[i4];
            ap[i4] = make_float4(0.f, 0.f, 0.f, 0.f);
            const float *wr = sm + N_SM_W1 + 4096 + i4 * 256;
            row_fma(acc, wr, f.x);
            row_fma(acc, wr + 64, f.y);
            row_fma(acc, wr + 128, f.z);
            row_fma(acc, wr + 192, f.w);
        }
        float m[64];
#pragma unroll
        for (int j = 0; j < 32; j++) {
            float2 a = unpack2(acc[j]);
            float2 b = *(const float2 *)(sm + N_SM_B1 + 2 * j);
            m[2 * j] = siluf(a.x + b.x);
            m[2 * j + 1] = siluf(a.y + b.y);
        }
#pragma unroll
        for (int j = 0; j < 32; j++) acc[j] = 0ull;
#pragma unroll
        for (int i2 = 0; i2 < 64; i2++) {
            row_fma(acc, sm + N_SM_W2 + i2 * 64, m[i2]);
        }
        float2 *hrow = (float2 *)(gh + (size_t)i * HH);
#pragma unroll
        for (int j = 0; j < 32; j++) {
            float2 a = unpack2(acc[j]);
            float2 b = *(const float2 *)(sm + N_SM_B2 + 2 * j);
            float2 hv = hrow[j];
            hv.x += a.x + b.x;
            hv.y += a.y + b.y;
            hrow[j] = hv;
        }
#pragma unroll
        for (int k = 0; k < 3; k++) {
            xout[3 * i + k] += g_dx[3 * i + k];
            g_dx[3 * i + k] = 0.f;
        }
    }
}

// ---------------- launch ----------------
extern "C" void kernel_launch(void *const *d_in, const int *in_sizes, int n_in,
                              void *d_out, int out_size) {
    const float *x   = (const float *)d_in[0];
    const int   *z   = (const int *)d_in[1];
    const float *t   = (const float *)d_in[2];
    const int   *ei  = (const int *)d_in[3];
    const float *emb = (const float *)d_in[4];
    const float *tw1 = (const float *)d_in[5];
    const float *tb1 = (const float *)d_in[6];
    const float *tw2 = (const float *)d_in[7];
    const float *tb2 = (const float *)d_in[8];
    const float *ew1 = (const float *)d_in[9];
    const float *eb1 = (const float *)d_in[10];
    const float *ew2 = (const float *)d_in[11];
    const float *eb2 = (const float *)d_in[12];
    const float *cw1 = (const float *)d_in[13];
    const float *cb1 = (const float *)d_in[14];
    const float *cw2 = (const float *)d_in[15];
    const float *cb2 = (const float *)d_in[16];
    const float *nw1 = (const float *)d_in[17];
    const float *nb1 = (const float *)d_in[18];
    const float *nw2 = (const float *)d_in[19];
    const float *nb2 = (const float *)d_in[20];
    float *out = (float *)d_out;

    cudaFuncSetAttribute(edge_kernel, cudaFuncAttributeMaxDynamicSharedMemorySize,
                         EDGE_SMEM_BYTES);
    cudaFuncSetAttribute(node_kernel, cudaFuncAttributeMaxDynamicSharedMemorySize,
                         NODE_SMEM_BYTES);
    cudaFuncSetAttribute(pre_kernel, cudaFuncAttributeMaxDynamicSharedMemorySize,
                         PRE_SMEM_BYTES);

    tmean_kernel<<<1, 64>>>(t, tw1, tb1, tw2, tb2);
    init_kernel<<<2048, 256>>>(x, z, emb, out);
    for (int l = 0; l < NLAYERS; l++) {
        pre_kernel<<<444, 128, PRE_SMEM_BYTES>>>(ew1 + l * 8256, eb1 + l * 64);
        edge_kernel<<<444, 128, EDGE_SMEM_BYTES>>>(
            out, ei, ew1 + l * 8256, ew2 + l * 4096, eb2 + l * 64,
            cw1 + l * 4096, cb1 + l * 64, cw2 + l * 64, cb2 + l);
        node_kernel<<<444, 128, NODE_SMEM_BYTES>>>(
            out, nw1 + l * 8192, nb1 + l * 64, nw2 + l * 4096, nb2 + l * 64);
    }
    (void)in_sizes; (void)n_in; (void)out_size;
}

// round 4
// speedup vs baseline: 4.8136x; 1.7472x over previous
#include <cuda_runtime.h>
#include <cstdint>

#define NN 100000
#define NE 1600000
#define HH 64
#define NLAYERS 3

// ---------------- device scratch ----------------
__device__ float4 g_h4[NN * 16];     // h: (N, 64)
__device__ float4 g_agg4[NN * 16];   // agg: (N, 64)
__device__ float4 g_a4[NN * 16];     // a[n] = h[n] @ W1[0:64] + e_b1
__device__ float4 g_b4[NN * 16];     // b[n] = h[n] @ W1[64:128]
__device__ float  g_dx[NN * 3];
__device__ float4 g_tmean4[16];

// ---------------- helpers ----------------
__device__ __forceinline__ float siluf(float v) {
    return __fdividef(v, 1.0f + __expf(-v));
}
__device__ __forceinline__ void red4(float *p, float a, float b, float c, float d) {
    asm volatile("red.global.add.v4.f32 [%0], {%1,%2,%3,%4};" ::"l"(p), "f"(a),
                 "f"(b), "f"(c), "f"(d)
                 : "memory");
}
__device__ __forceinline__ void red1(float *p, float a) {
    asm volatile("red.global.add.f32 [%0], %1;" ::"l"(p), "f"(a) : "memory");
}
__device__ __forceinline__ uint32_t to_tf32(float f) {
    uint32_t r;
    asm("cvt.rna.tf32.f32 %0, %1;" : "=r"(r) : "f"(f));
    return r;
}
__device__ __forceinline__ void mma_tf32(float (&d)[4], const uint32_t (&a)[4],
                                         const uint32_t (&b)[2]) {
    asm volatile(
        "mma.sync.aligned.m16n8k8.row.col.f32.tf32.tf32.f32 "
        "{%0,%1,%2,%3}, {%4,%5,%6,%7}, {%8,%9}, {%0,%1,%2,%3};\n"
        : "+f"(d[0]), "+f"(d[1]), "+f"(d[2]), "+f"(d[3])
        : "r"(a[0]), "r"(a[1]), "r"(a[2]), "r"(a[3]), "r"(b[0]), "r"(b[1]));
}

// 32xK A (row-major, stride SA) @ K x 64 B (stored transposed [n][k], stride SB)
template <int SA, int SB, int KS>
__device__ __forceinline__ void gemmT(float (&acc)[2][8][4],
                                      const uint32_t *__restrict__ A,
                                      const uint32_t *__restrict__ B, int g, int q) {
#pragma unroll
    for (int k = 0; k < KS; k++) {
        uint32_t Bf[8][2];
#pragma unroll
        for (int n = 0; n < 8; n++) {
            const uint32_t *bp = B + (8 * n + g) * SB + 8 * k + q;
            Bf[n][0] = bp[0];
            Bf[n][1] = bp[4];
        }
#pragma unroll
        for (int m = 0; m < 2; m++) {
            const uint32_t *ap = A + (16 * m + g) * SA + 8 * k + q;
            uint32_t Af[4];
            Af[0] = ap[0];
            Af[1] = ap[8 * SA];
            Af[2] = ap[4];
            Af[3] = ap[8 * SA + 4];
#pragma unroll
            for (int n = 0; n < 8; n++) mma_tf32(acc[m][n], Af, Bf[n]);
        }
    }
}
__device__ __forceinline__ void zacc(float (&acc)[2][8][4]) {
#pragma unroll
    for (int m = 0; m < 2; m++)
#pragma unroll
        for (int n = 0; n < 8; n++)
#pragma unroll
            for (int v = 0; v < 4; v++) acc[m][n][v] = 0.f;
}

__device__ __forceinline__ void cp_s(float *dst, const float *__restrict__ src,
                                     int nfloats, int tid, int nthr) {
    const float4 *s4 = (const float4 *)src;
    float4 *d4 = (float4 *)dst;
    for (int k = tid; k < (nfloats >> 2); k += nthr) d4[k] = s4[k];
}

// ---------------- time-embedding mean ----------------
__global__ void tmean_kernel(const float *__restrict__ t,
                             const float *__restrict__ w1,
                             const float *__restrict__ b1,
                             const float *__restrict__ w2,
                             const float *__restrict__ b2) {
    __shared__ float sS[16 * 64];
    int j = threadIdx.x;
    float w1j = w1[j], b1j = b1[j];
    for (int b = 0; b < 16; b++) sS[b * 64 + j] = siluf(t[b] * w1j + b1j);
    __syncthreads();
    float accm = 0.f;
    for (int b = 0; b < 16; b++) {
        float s = b2[j];
        for (int k = 0; k < 64; k++) s += sS[b * 64 + k] * w2[k * 64 + j];
        accm += s;
    }
    ((float *)g_tmean4)[j] = accm * (1.0f / 16.0f);
}

// ---------------- init ----------------
__global__ void init_kernel(const float *__restrict__ x, const int *__restrict__ z,
                            const float *__restrict__ emb, float *__restrict__ out) {
    int tid = blockIdx.x * blockDim.x + threadIdx.x;
    int stride = gridDim.x * blockDim.x;
    const float4 *emb4 = (const float4 *)emb;
    for (int idx = tid; idx < NN * 16; idx += stride) {
        int i = idx >> 4, qq = idx & 15;
        float4 e = emb4[z[i] * 16 + qq];
        float4 tm = g_tmean4[qq];
        float4 r;
        r.x = e.x + tm.x; r.y = e.y + tm.y; r.z = e.z + tm.z; r.w = e.w + tm.w;
        g_h4[idx] = r;
        g_agg4[idx] = make_float4(0.f, 0.f, 0.f, 0.f);
    }
    for (int idx = tid; idx < NN * 3; idx += stride) {
        out[idx] = x[idx];
        g_dx[idx] = 0.f;
    }
}

// ---------------- pre0: a,b for layer 0 (tensor core) ----------------
// smem words:
#define PR_AT 0
#define PR_BT 4352
#define PR_EB1 8704
#define PR_WARP 8768
#define PR_WARP_WORDS 2176
#define PRE_SMEM_WORDS (PR_WARP + 8 * PR_WARP_WORDS)
#define PRE_SMEM_BYTES (PRE_SMEM_WORDS * 4)

__global__ void __launch_bounds__(256, 2)
pre0_kernel(const float *__restrict__ W1, const float *__restrict__ B1) {
    extern __shared__ float sm[];
    uint32_t *smu = (uint32_t *)sm;
    int tid = threadIdx.x;
    for (int idx = tid; idx < 4096; idx += 256) {
        int kk = idx >> 6, nn = idx & 63;
        smu[PR_AT + nn * 68 + kk] = to_tf32(W1[kk * 64 + nn]);
        smu[PR_BT + nn * 68 + kk] = to_tf32(W1[(64 + kk) * 64 + nn]);
    }
    cp_s(sm + PR_EB1, B1, 64, tid, 256);
    __syncthreads();

    const int lane = tid & 31, wid = tid >> 5;
    const int g = lane >> 2, q = lane & 3;
    uint32_t *buf = smu + PR_WARP + wid * PR_WARP_WORDS;
    const float *gh = (const float *)g_h4;
    float *gaA = (float *)g_a4;
    float *gaB = (float *)g_b4;

    int gwarp = blockIdx.x * 8 + wid;
    int nwarps = gridDim.x * 8;
    for (int i0 = gwarp * 32; i0 < NN; i0 += nwarps * 32) {
        // stage h as tf32 (lane = col pair)
#pragma unroll
        for (int t = 0; t < 32; t++) {
            float2 hv = *(const float2 *)(gh + (size_t)(i0 + t) * HH + 2 * lane);
            uint2 p;
            p.x = to_tf32(hv.x);
            p.y = to_tf32(hv.y);
            *(uint2 *)(buf + t * 68 + 2 * lane) = p;
        }
        __syncwarp();
        float acc[2][8][4];
        zacc(acc);
        gemmT<68, 68, 8>(acc, buf, smu + PR_AT, g, q);
#pragma unroll
        for (int m = 0; m < 2; m++) {
            int r0 = 16 * m + g, r1 = r0 + 8;
#pragma unroll
            for (int n = 0; n < 8; n++) {
                int c0 = 8 * n + 2 * q;
                float2 bb = *(const float2 *)(sm + PR_EB1 + c0);
                float2 v0 = {acc[m][n][0] + bb.x, acc[m][n][1] + bb.y};
                float2 v1 = {acc[m][n][2] + bb.x, acc[m][n][3] + bb.y};
                *(float2 *)(gaA + (size_t)(i0 + r0) * HH + c0) = v0;
                *(float2 *)(gaA + (size_t)(i0 + r1) * HH + c0) = v1;
            }
        }
        zacc(acc);
        gemmT<68, 68, 8>(acc, buf, smu + PR_BT, g, q);
#pragma unroll
        for (int m = 0; m < 2; m++) {
            int r0 = 16 * m + g, r1 = r0 + 8;
#pragma unroll
            for (int n = 0; n < 8; n++) {
                int c0 = 8 * n + 2 * q;
                float2 v0 = {acc[m][n][0], acc[m][n][1]};
                float2 v1 = {acc[m][n][2], acc[m][n][3]};
                *(float2 *)(gaB + (size_t)(i0 + r0) * HH + c0) = v0;
                *(float2 *)(gaB + (size_t)(i0 + r1) * HH + c0) = v1;
            }
        }
        __syncwarp();
    }
}

// ---------------- edge kernel (tensor core) ----------------
#define E_W2T 0
#define E_C1T 4352
#define E_B2 8704
#define E_CB1 8768
#define E_C2 8832
#define E_W129 8896
#define E_CB2 8960
#define E_WARP 8964
#define E_WARP_WORDS 2208
#define EDGE_SMEM_WORDS (E_WARP + 4 * E_WARP_WORDS)
#define EDGE_SMEM_BYTES (EDGE_SMEM_WORDS * 4)

__global__ void __launch_bounds__(128, 3)
edge_kernel(const float *__restrict__ xin, const int *__restrict__ ei,
            const float *__restrict__ W1, const float *__restrict__ W2,
            const float *__restrict__ B2, const float *__restrict__ C1,
            const float *__restrict__ Cb1, const float *__restrict__ C2,
            const float *__restrict__ Cb2) {
    extern __shared__ float sm[];
    uint32_t *smu = (uint32_t *)sm;
    int tid = threadIdx.x;

    for (int idx = tid; idx < 4096; idx += 128) {
        int kk = idx >> 6, nn = idx & 63;
        smu[E_W2T + nn * 68 + kk] = to_tf32(W2[idx]);
        smu[E_C1T + nn * 68 + kk] = to_tf32(C1[idx]);
    }
    cp_s(sm + E_B2, B2, 64, tid, 128);
    cp_s(sm + E_CB1, Cb1, 64, tid, 128);
    cp_s(sm + E_C2, C2, 64, tid, 128);
    cp_s(sm + E_W129, W1 + 8192, 64, tid, 128);
    if (tid == 0) sm[E_CB2] = Cb2[0];
    __syncthreads();

    const int lane = tid & 31;
    const int wid = tid >> 5;
    const int g = lane >> 2;
    const int q = lane & 3;
    uint32_t *m1s = smu + E_WARP + wid * E_WARP_WORDS;
    float *cwbuf = sm + E_WARP + wid * E_WARP_WORDS + 2176;

    const float *ga = (const float *)g_a4;
    const float *gb = (const float *)g_b4;
    float *gagg = (float *)g_agg4;

    const float w129x = sm[E_W129 + 2 * lane];
    const float w129y = sm[E_W129 + 2 * lane + 1];
    const float cb2v = sm[E_CB2];

    int gwarp = blockIdx.x * 4 + wid;
    int nwarps = gridDim.x * 4;

    for (int eb = gwarp * 32; eb < NE; eb += nwarps * 32) {
        int e = eb + lane;
        int s = ei[e];
        int d = ei[NE + e];
        float ax = xin[3 * d + 0] - xin[3 * s + 0];
        float ay = xin[3 * d + 1] - xin[3 * s + 1];
        float az = xin[3 * d + 2] - xin[3 * s + 2];
        float d2 = ax * ax + ay * ay + az * az;

        // m1 = silu(a[d] + b[s] + d2*w129)
#pragma unroll
        for (int t = 0; t < 32; t++) {
            int dt = __shfl_sync(0xffffffffu, d, t);
            int st = __shfl_sync(0xffffffffu, s, t);
            float d2t = __shfl_sync(0xffffffffu, d2, t);
            float2 av = *(const float2 *)(ga + (size_t)dt * HH + 2 * lane);
            float2 bv = *(const float2 *)(gb + (size_t)st * HH + 2 * lane);
            float m0 = siluf(fmaf(d2t, w129x, av.x + bv.x));
            float m1v = siluf(fmaf(d2t, w129y, av.y + bv.y));
            uint2 pk;
            pk.x = to_tf32(m0);
            pk.y = to_tf32(m1v);
            *(uint2 *)(m1s + t * 68 + 2 * lane) = pk;
        }
        __syncwarp();

        // GEMM2: m = silu(m1 @ W2 + b2)
        float acc[2][8][4];
        zacc(acc);
        gemmT<68, 68, 8>(acc, m1s, smu + E_W2T, g, q);
        __syncwarp();

#pragma unroll
        for (int m = 0; m < 2; m++) {
            int r0 = 16 * m + g;
            int r1 = r0 + 8;
#pragma unroll
            for (int n = 0; n < 8; n++) {
                int c0 = 8 * n + 2 * q;
                float b2x = sm[E_B2 + c0], b2y = sm[E_B2 + c0 + 1];
                uint2 p0, p1;
                p0.x = to_tf32(siluf(acc[m][n][0] + b2x));
                p0.y = to_tf32(siluf(acc[m][n][1] + b2y));
                p1.x = to_tf32(siluf(acc[m][n][2] + b2x));
                p1.y = to_tf32(siluf(acc[m][n][3] + b2y));
                *(uint2 *)(m1s + r0 * 68 + c0) = p0;
                *(uint2 *)(m1s + r1 * 68 + c0) = p1;
                acc[m][n][0] = 0.f; acc[m][n][1] = 0.f;
                acc[m][n][2] = 0.f; acc[m][n][3] = 0.f;
            }
        }
        __syncwarp();

        // agg scatter: row-coalesced red4 from staged m (2 rows / iter)
#pragma unroll
        for (int tt = 0; tt < 32; tt += 2) {
            int row = tt + (lane >> 4);
            int q4 = lane & 15;
            int dt = __shfl_sync(0xffffffffu, d, row);
            const float *mp = (const float *)m1s + row * 68 + 4 * q4;
            float4 v = *(const float4 *)mp;
            red4(gagg + (size_t)dt * HH + 4 * q4, v.x, v.y, v.z, v.w);
        }

        // coord MLP
        gemmT<68, 68, 8>(acc, m1s, smu + E_C1T, g, q);

        float cwp[2][2] = {{0.f, 0.f}, {0.f, 0.f}};
#pragma unroll
        for (int m = 0; m < 2; m++)
#pragma unroll
            for (int n = 0; n < 8; n++) {
                int c0 = 8 * n + 2 * q;
                float cb1x = sm[E_CB1 + c0], cb1y = sm[E_CB1 + c0 + 1];
                float c2x = sm[E_C2 + c0], c2y = sm[E_C2 + c0 + 1];
                cwp[m][0] += siluf(acc[m][n][0] + cb1x) * c2x +
                             siluf(acc[m][n][1] + cb1y) * c2y;
                cwp[m][1] += siluf(acc[m][n][2] + cb1x) * c2x +
                             siluf(acc[m][n][3] + cb1y) * c2y;
            }
#pragma unroll
        for (int ofs = 1; ofs <= 2; ofs <<= 1) {
#pragma unroll
            for (int m = 0; m < 2; m++) {
                cwp[m][0] += __shfl_xor_sync(0xffffffffu, cwp[m][0], ofs);
                cwp[m][1] += __shfl_xor_sync(0xffffffffu, cwp[m][1], ofs);
            }
        }
        if (q == 0) {
#pragma unroll
            for (int m = 0; m < 2; m++) {
                cwbuf[16 * m + g] = cwp[m][0] + cb2v;
                cwbuf[16 * m + g + 8] = cwp[m][1] + cb2v;
            }
        }
        __syncwarp();

        float cw = cwbuf[lane];
        red1(&g_dx[3 * d + 0], ax * cw);
        red1(&g_dx[3 * d + 1], ay * cw);
        red1(&g_dx[3 * d + 2], az * cw);
        __syncwarp();
    }
}

// ---------------- node kernel (tensor core, fused next-layer pre) ----------------
// smem words:
#define ND_W1T 0
#define ND_W2T 8448
#define ND_AT 12800
#define ND_BT 17152
#define ND_NB1 21504
#define ND_NB2 21568
#define ND_EB1 21632
#define ND_WARP 21696
#define ND_WARP_WORDS 4224
#define NODE_SMEM_WORDS (ND_WARP + 8 * ND_WARP_WORDS)
#define NODE_SMEM_BYTES (NODE_SMEM_WORDS * 4)

__global__ void __launch_bounds__(256, 1)
node_kernel(float *__restrict__ xout, const float *__restrict__ NW1,
            const float *__restrict__ NB1, const float *__restrict__ NW2,
            const float *__restrict__ NB2, const float *__restrict__ EW1n,
            const float *__restrict__ EB1n, int do_pre) {
    extern __shared__ float sm[];
    uint32_t *smu = (uint32_t *)sm;
    int tid = threadIdx.x;

    for (int idx = tid; idx < 8192; idx += 256) {
        int kk = idx >> 6, nn = idx & 63;
        smu[ND_W1T + nn * 132 + kk] = to_tf32(NW1[kk * 64 + nn]);
    }
    for (int idx = tid; idx < 4096; idx += 256) {
        int kk = idx >> 6, nn = idx & 63;
        smu[ND_W2T + nn * 68 + kk] = to_tf32(NW2[idx]);
        if (do_pre) {
            smu[ND_AT + nn * 68 + kk] = to_tf32(EW1n[kk * 64 + nn]);
            smu[ND_BT + nn * 68 + kk] = to_tf32(EW1n[(64 + kk) * 64 + nn]);
        }
    }
    cp_s(sm + ND_NB1, NB1, 64, tid, 256);
    cp_s(sm + ND_NB2, NB2, 64, tid, 256);
    if (do_pre) cp_s(sm + ND_EB1, EB1n, 64, tid, 256);
    __syncthreads();

    const int lane = tid & 31, wid = tid >> 5;
    const int g = lane >> 2, q = lane & 3;
    uint32_t *buf = smu + ND_WARP + wid * ND_WARP_WORDS;

    float *gh = (float *)g_h4;
    float *gagg = (float *)g_agg4;
    float *gaA = (float *)g_a4;
    float *gaB = (float *)g_b4;

    int gwarp = blockIdx.x * 8 + wid;
    int nwarps = gridDim.x * 8;

    for (int i0 = gwarp * 32; i0 < NN; i0 += nwarps * 32) {
        // stage nf = [h, agg] as tf32 (stride 132); zero agg
#pragma unroll
        for (int t = 0; t < 32; t++) {
            size_t ro = (size_t)(i0 + t) * HH;
            float2 hv = *(const float2 *)(gh + ro + 2 * lane);
            float2 av = *(const float2 *)(gagg + ro + 2 * lane);
            *(float2 *)(gagg + ro + 2 * lane) = make_float2(0.f, 0.f);
            uint2 ph, pa;
            ph.x = to_tf32(hv.x); ph.y = to_tf32(hv.y);
            pa.x = to_tf32(av.x); pa.y = to_tf32(av.y);
            *(uint2 *)(buf + t * 132 + 2 * lane) = ph;
            *(uint2 *)(buf + t * 132 + 64 + 2 * lane) = pa;
        }
        __syncwarp();

        float acc[2][8][4];
        zacc(acc);
        gemmT<132, 132, 16>(acc, buf, smu + ND_W1T, g, q);
        __syncwarp();

        // m1 = silu(acc + nb1) -> restage stride 68
#pragma unroll
        for (int m = 0; m < 2; m++) {
            int r0 = 16 * m + g, r1 = r0 + 8;
#pragma unroll
            for (int n = 0; n < 8; n++) {
                int c0 = 8 * n + 2 * q;
                float2 bb = *(const float2 *)(sm + ND_NB1 + c0);
                uint2 p0, p1;
                p0.x = to_tf32(siluf(acc[m][n][0] + bb.x));
                p0.y = to_tf32(siluf(acc[m][n][1] + bb.y));
                p1.x = to_tf32(siluf(acc[m][n][2] + bb.x));
                p1.y = to_tf32(siluf(acc[m][n][3] + bb.y));
                *(uint2 *)(buf + r0 * 68 + c0) = p0;
                *(uint2 *)(buf + r1 * 68 + c0) = p1;
            }
        }
        __syncwarp();

        zacc(acc);
        gemmT<68, 68, 8>(acc, buf, smu + ND_W2T, g, q);
        __syncwarp();

        // hnew = h_old + acc + nb2 -> global h, and restage tf32 for pre gemms
#pragma unroll
        for (int m = 0; m < 2; m++) {
            int r0 = 16 * m + g, r1 = r0 + 8;
            float *h0 = gh + (size_t)(i0 + r0) * HH;
            float *h1 = gh + (size_t)(i0 + r1) * HH;
#pragma unroll
            for (int n = 0; n < 8; n++) {
                int c0 = 8 * n + 2 * q;
                float2 bb = *(const float2 *)(sm + ND_NB2 + c0);
                float2 o0 = *(const float2 *)(h0 + c0);
                float2 o1 = *(const float2 *)(h1 + c0);
                o0.x += acc[m][n][0] + bb.x;
                o0.y += acc[m][n][1] + bb.y;
                o1.x += acc[m][n][2] + bb.x;
                o1.y += acc[m][n][3] + bb.y;
                *(float2 *)(h0 + c0) = o0;
                *(float2 *)(h1 + c0) = o1;
                if (do_pre) {
                    uint2 p0, p1;
                    p0.x = to_tf32(o0.x); p0.y = to_tf32(o0.y);
                    p1.x = to_tf32(o1.x); p1.y = to_tf32(o1.y);
                    *(uint2 *)(buf + r0 * 68 + c0) = p0;
                    *(uint2 *)(buf + r1 * 68 + c0) = p1;
                }
            }
        }
        __syncwarp();

        if (do_pre) {
            zacc(acc);
            gemmT<68, 68, 8>(acc, buf, smu + ND_AT, g, q);
#pragma unroll
            for (int m = 0; m < 2; m++) {
                int r0 = 16 * m + g, r1 = r0 + 8;
#pragma unroll
                for (int n = 0; n < 8; n++) {
                    int c0 = 8 * n + 2 * q;
                    float2 bb = *(const float2 *)(sm + ND_EB1 + c0);
                    float2 v0 = {acc[m][n][0] + bb.x, acc[m][n][1] + bb.y};
                    float2 v1 = {acc[m][n][2] + bb.x, acc[m][n][3] + bb.y};
                    *(float2 *)(gaA + (size_t)(i0 + r0) * HH + c0) = v0;
                    *(float2 *)(gaA + (size_t)(i0 + r1) * HH + c0) = v1;
                }
            }
            zacc(acc);
            gemmT<68, 68, 8>(acc, buf, smu + ND_BT, g, q);
#pragma unroll
            for (int m = 0; m < 2; m++) {
                int r0 = 16 * m + g, r1 = r0 + 8;
#pragma unroll
                for (int n = 0; n < 8; n++) {
                    int c0 = 8 * n + 2 * q;
                    float2 v0 = {acc[m][n][0], acc[m][n][1]};
                    float2 v1 = {acc[m][n][2], acc[m][n][3]};
                    *(float2 *)(gaB + (size_t)(i0 + r0) * HH + c0) = v0;
                    *(float2 *)(gaB + (size_t)(i0 + r1) * HH + c0) = v1;
                }
            }
        }

        // x += dx; reset dx (lane = node)
        int i = i0 + lane;
#pragma unroll
        for (int k = 0; k < 3; k++) {
            xout[3 * i + k] += g_dx[3 * i + k];
            g_dx[3 * i + k] = 0.f;
        }
        __syncwarp();
    }
}

// ---------------- launch ----------------
extern "C" void kernel_launch(void *const *d_in, const int *in_sizes, int n_in,
                              void *d_out, int out_size) {
    const float *x   = (const float *)d_in[0];
    const int   *z   = (const int *)d_in[1];
    const float *t   = (const float *)d_in[2];
    const int   *ei  = (const int *)d_in[3];
    const float *emb = (const float *)d_in[4];
    const float *tw1 = (const float *)d_in[5];
    const float *tb1 = (const float *)d_in[6];
    const float *tw2 = (const float *)d_in[7];
    const float *tb2 = (const float *)d_in[8];
    const float *ew1 = (const float *)d_in[9];
    const float *eb1 = (const float *)d_in[10];
    const float *ew2 = (const float *)d_in[11];
    const float *eb2 = (const float *)d_in[12];
    const float *cw1 = (const float *)d_in[13];
    const float *cb1 = (const float *)d_in[14];
    const float *cw2 = (const float *)d_in[15];
    const float *cb2 = (const float *)d_in[16];
    const float *nw1 = (const float *)d_in[17];
    const float *nb1 = (const float *)d_in[18];
    const float *nw2 = (const float *)d_in[19];
    const float *nb2 = (const float *)d_in[20];
    float *out = (float *)d_out;

    cudaFuncSetAttribute(edge_kernel, cudaFuncAttributeMaxDynamicSharedMemorySize,
                         EDGE_SMEM_BYTES);
    cudaFuncSetAttribute(node_kernel, cudaFuncAttributeMaxDynamicSharedMemorySize,
                         NODE_SMEM_BYTES);
    cudaFuncSetAttribute(pre0_kernel, cudaFuncAttributeMaxDynamicSharedMemorySize,
                         PRE_SMEM_BYTES);

    tmean_kernel<<<1, 64>>>(t, tw1, tb1, tw2, tb2);
    init_kernel<<<2048, 256>>>(x, z, emb, out);
    pre0_kernel<<<296, 256, PRE_SMEM_BYTES>>>(ew1, eb1);
    for (int l = 0; l < NLAYERS; l++) {
        edge_kernel<<<444, 128, EDGE_SMEM_BYTES>>>(
            out, ei, ew1 + l * 8256, ew2 + l * 4096, eb2 + l * 64,
            cw1 + l * 4096, cb1 + l * 64, cw2 + l * 64, cb2 + l);
        int do_pre = (l + 1 < NLAYERS);
        node_kernel<<<148, 256, NODE_SMEM_BYTES>>>(
            out, nw1 + l * 8192, nb1 + l * 64, nw2 + l * 4096, nb2 + l * 64,
            do_pre ? (ew1 + (l + 1) * 8256) : ew1,
            do_pre ? (eb1 + (l + 1) * 64) : eb1, do_pre);
    }
    (void)in_sizes; (void)n_in; (void)out_size;
}

// round 6
// speedup vs baseline: 5.7196x; 1.1882x over previous
#include <cuda_runtime.h>
#include <cstdint>

#define NN 100000
#define NE 1600000
#define HH 64
#define NLAYERS 3

// ---------------- device scratch ----------------
__device__ float4 g_h4[NN * 16];     // h: (N, 64)
__device__ float4 g_agg4[NN * 16];   // agg: (N, 64)
__device__ float4 g_a4[NN * 16];     // a[n] = h[n] @ W1[0:64] + e_b1
__device__ float4 g_b4[NN * 16];     // b[n] = h[n] @ W1[64:128]
__device__ float  g_dx[NN * 3];
__device__ float4 g_tmean4[16];

// ---------------- helpers ----------------
// silu(x) = x*sigmoid(x) = 0.5*x*(1+tanh(0.5*x)) ; tanh.approx = 1 MUFU
__device__ __forceinline__ float siluf(float v) {
    float th;
    float hv = 0.5f * v;
    asm("tanh.approx.f32 %0, %1;" : "=f"(th) : "f"(hv));
    return fmaf(hv, th, hv);
}
// exact silu for the tiny tmean path
__device__ __forceinline__ float silux(float v) {
    return __fdividef(v, 1.0f + __expf(-v));
}
__device__ __forceinline__ void red4(float *p, float a, float b, float c, float d) {
    asm volatile("red.global.add.v4.f32 [%0], {%1,%2,%3,%4};" ::"l"(p), "f"(a),
                 "f"(b), "f"(c), "f"(d)
                 : "memory");
}
__device__ __forceinline__ void red1(float *p, float a) {
    asm volatile("red.global.add.f32 [%0], %1;" ::"l"(p), "f"(a) : "memory");
}
__device__ __forceinline__ uint32_t to_tf32(float f) {
    uint32_t r;
    asm("cvt.rna.tf32.f32 %0, %1;" : "=r"(r) : "f"(f));
    return r;
}
__device__ __forceinline__ void mma_tf32(float (&d)[4], const uint32_t (&a)[4],
                                         const uint32_t (&b)[2]) {
    asm volatile(
        "mma.sync.aligned.m16n8k8.row.col.f32.tf32.tf32.f32 "
        "{%0,%1,%2,%3}, {%4,%5,%6,%7}, {%8,%9}, {%0,%1,%2,%3};\n"
        : "+f"(d[0]), "+f"(d[1]), "+f"(d[2]), "+f"(d[3])
        : "r"(a[0]), "r"(a[1]), "r"(a[2]), "r"(a[3]), "r"(b[0]), "r"(b[1]));
}

// 32xK A (row-major, stride SA) @ K x 64 B (transposed [n][k], stride SB)
template <int SA, int SB, int KS>
__device__ __forceinline__ void gemmT(float (&acc)[2][8][4],
                                      const uint32_t *__restrict__ A,
                                      const uint32_t *__restrict__ B, int g, int q) {
#pragma unroll
    for (int k = 0; k < KS; k++) {
        uint32_t Bf[8][2];
#pragma unroll
        for (int n = 0; n < 8; n++) {
            const uint32_t *bp = B + (8 * n + g) * SB + 8 * k + q;
            Bf[n][0] = bp[0];
            Bf[n][1] = bp[4];
        }
#pragma unroll
        for (int m = 0; m < 2; m++) {
            const uint32_t *ap = A + (16 * m + g) * SA + 8 * k + q;
            uint32_t Af[4];
            Af[0] = ap[0];
            Af[1] = ap[8 * SA];
            Af[2] = ap[4];
            Af[3] = ap[8 * SA + 4];
#pragma unroll
            for (int n = 0; n < 8; n++) mma_tf32(acc[m][n], Af, Bf[n]);
        }
    }
}

// edge gemm: A stride 68; B in fragment-pair layout stride 72
// BF[nn*72 + 8k + 2q + half] = W[8k + q + 4*half][nn]  -> one LDS.64 per (k,n)
template <int KS>
__device__ __forceinline__ void gemmF(float (&acc)[2][8][4],
                                      const uint32_t *__restrict__ A,
                                      const uint32_t *__restrict__ BF, int g,
                                      int q) {
#pragma unroll
    for (int k = 0; k < KS; k++) {
        uint32_t Af0[4], Af1[4];
        const uint32_t *ap0 = A + g * 68 + 8 * k + q;
        Af0[0] = ap0[0];
        Af0[1] = ap0[8 * 68];
        Af0[2] = ap0[4];
        Af0[3] = ap0[8 * 68 + 4];
        const uint32_t *ap1 = ap0 + 16 * 68;
        Af1[0] = ap1[0];
        Af1[1] = ap1[8 * 68];
        Af1[2] = ap1[4];
        Af1[3] = ap1[8 * 68 + 4];
#pragma unroll
        for (int n = 0; n < 8; n++) {
            uint2 bv = *(const uint2 *)(BF + (8 * n + g) * 72 + 8 * k + 2 * q);
            uint32_t Bv[2] = {bv.x, bv.y};
            mma_tf32(acc[0][n], Af0, Bv);
            mma_tf32(acc[1][n], Af1, Bv);
        }
    }
}

__device__ __forceinline__ void zacc(float (&acc)[2][8][4]) {
#pragma unroll
    for (int m = 0; m < 2; m++)
#pragma unroll
        for (int n = 0; n < 8; n++)
#pragma unroll
            for (int v = 0; v < 4; v++) acc[m][n][v] = 0.f;
}

__device__ __forceinline__ void cp_s(float *dst, const float *__restrict__ src,
                                     int nfloats, int tid, int nthr) {
    const float4 *s4 = (const float4 *)src;
    float4 *d4 = (float4 *)dst;
    for (int k = tid; k < (nfloats >> 2); k += nthr) d4[k] = s4[k];
}

// ---------------- time-embedding mean ----------------
__global__ void tmean_kernel(const float *__restrict__ t,
                             const float *__restrict__ w1,
                             const float *__restrict__ b1,
                             const float *__restrict__ w2,
                             const float *__restrict__ b2) {
    __shared__ float sS[16 * 64];
    int j = threadIdx.x;
    float w1j = w1[j], b1j = b1[j];
    for (int b = 0; b < 16; b++) sS[b * 64 + j] = silux(t[b] * w1j + b1j);
    __syncthreads();
    float accm = 0.f;
    for (int b = 0; b < 16; b++) {
        float s = b2[j];
        for (int k = 0; k < 64; k++) s += sS[b * 64 + k] * w2[k * 64 + j];
        accm += s;
    }
    ((float *)g_tmean4)[j] = accm * (1.0f / 16.0f);
}

// ---------------- init ----------------
__global__ void init_kernel(const float *__restrict__ x, const int *__restrict__ z,
                            const float *__restrict__ emb, float *__restrict__ out) {
    int tid = blockIdx.x * blockDim.x + threadIdx.x;
    int stride = gridDim.x * blockDim.x;
    const float4 *emb4 = (const float4 *)emb;
    for (int idx = tid; idx < NN * 16; idx += stride) {
        int i = idx >> 4, qq = idx & 15;
        float4 e = emb4[z[i] * 16 + qq];
        float4 tm = g_tmean4[qq];
        float4 r;
        r.x = e.x + tm.x; r.y = e.y + tm.y; r.z = e.z + tm.z; r.w = e.w + tm.w;
        g_h4[idx] = r;
        g_agg4[idx] = make_float4(0.f, 0.f, 0.f, 0.f);
    }
    for (int idx = tid; idx < NN * 3; idx += stride) {
        out[idx] = x[idx];
        g_dx[idx] = 0.f;
    }
}

// ---------------- pre0: a,b for layer 0 (tensor core) ----------------
#define PR_AT 0
#define PR_BT 4352
#define PR_EB1 8704
#define PR_WARP 8768
#define PR_WARP_WORDS 2176
#define PRE_SMEM_WORDS (PR_WARP + 8 * PR_WARP_WORDS)
#define PRE_SMEM_BYTES (PRE_SMEM_WORDS * 4)

__global__ void __launch_bounds__(256, 2)
pre0_kernel(const float *__restrict__ W1, const float *__restrict__ B1) {
    extern __shared__ float sm[];
    uint32_t *smu = (uint32_t *)sm;
    int tid = threadIdx.x;
    for (int idx = tid; idx < 4096; idx += 256) {
        int kk = idx >> 6, nn = idx & 63;
        smu[PR_AT + nn * 68 + kk] = to_tf32(W1[kk * 64 + nn]);
        smu[PR_BT + nn * 68 + kk] = to_tf32(W1[(64 + kk) * 64 + nn]);
    }
    cp_s(sm + PR_EB1, B1, 64, tid, 256);
    __syncthreads();

    const int lane = tid & 31, wid = tid >> 5;
    const int g = lane >> 2, q = lane & 3;
    uint32_t *buf = smu + PR_WARP + wid * PR_WARP_WORDS;
    const float *gh = (const float *)g_h4;
    float *gaA = (float *)g_a4;
    float *gaB = (float *)g_b4;

    int gwarp = blockIdx.x * 8 + wid;
    int nwarps = gridDim.x * 8;
    for (int i0 = gwarp * 32; i0 < NN; i0 += nwarps * 32) {
#pragma unroll
        for (int t = 0; t < 32; t++) {
            float2 hv = *(const float2 *)(gh + (size_t)(i0 + t) * HH + 2 * lane);
            uint2 p;
            p.x = to_tf32(hv.x);
            p.y = to_tf32(hv.y);
            *(uint2 *)(buf + t * 68 + 2 * lane) = p;
        }
        __syncwarp();
        float acc[2][8][4];
        zacc(acc);
        gemmT<68, 68, 8>(acc, buf, smu + PR_AT, g, q);
#pragma unroll
        for (int m = 0; m < 2; m++) {
            int r0 = 16 * m + g, r1 = r0 + 8;
#pragma unroll
            for (int n = 0; n < 8; n++) {
                int c0 = 8 * n + 2 * q;
                float2 bb = *(const float2 *)(sm + PR_EB1 + c0);
                float2 v0 = {acc[m][n][0] + bb.x, acc[m][n][1] + bb.y};
                float2 v1 = {acc[m][n][2] + bb.x, acc[m][n][3] + bb.y};
                *(float2 *)(gaA + (size_t)(i0 + r0) * HH + c0) = v0;
                *(float2 *)(gaA + (size_t)(i0 + r1) * HH + c0) = v1;
            }
        }
        zacc(acc);
        gemmT<68, 68, 8>(acc, buf, smu + PR_BT, g, q);
#pragma unroll
        for (int m = 0; m < 2; m++) {
            int r0 = 16 * m + g, r1 = r0 + 8;
#pragma unroll
            for (int n = 0; n < 8; n++) {
                int c0 = 8 * n + 2 * q;
                float2 v0 = {acc[m][n][0], acc[m][n][1]};
                float2 v1 = {acc[m][n][2], acc[m][n][3]};
                *(float2 *)(gaB + (size_t)(i0 + r0) * HH + c0) = v0;
                *(float2 *)(gaB + (size_t)(i0 + r1) * HH + c0) = v1;
            }
        }
        __syncwarp();
    }
}

// ---------------- edge kernel (tensor core, 256 thr, 2 CTA/SM) ----------------
// smem words:
#define E_W2T 0        /* 64 x 72 fragment-pair layout */
#define E_C1T 4608
#define E_B2 9216
#define E_CB1 9280
#define E_C2 9344
#define E_W129 9408
#define E_CB2 9472
#define E_WARP 9480
#define E_WARP_WORDS 2208   /* m1s 2176 + cwbuf 32 */
#define EDGE_SMEM_WORDS (E_WARP + 8 * E_WARP_WORDS)
#define EDGE_SMEM_BYTES (EDGE_SMEM_WORDS * 4)

__global__ void __launch_bounds__(256, 2)
edge_kernel(const float *__restrict__ xin, const int *__restrict__ ei,
            const float *__restrict__ W1, const float *__restrict__ W2,
            const float *__restrict__ B2, const float *__restrict__ C1,
            const float *__restrict__ Cb1, const float *__restrict__ C2,
            const float *__restrict__ Cb2) {
    extern __shared__ float sm[];
    uint32_t *smu = (uint32_t *)sm;
    int tid = threadIdx.x;

    // stage weights in fragment-pair layout (stride 72)
    for (int idx = tid; idx < 4096; idx += 256) {
        int nn = idx >> 6, slot = idx & 63;
        int k = slot >> 3, r = slot & 7;
        int qq = r >> 1, half = r & 1;
        int krow = 8 * k + qq + 4 * half;
        smu[E_W2T + nn * 72 + slot] = to_tf32(W2[krow * 64 + nn]);
        smu[E_C1T + nn * 72 + slot] = to_tf32(C1[krow * 64 + nn]);
    }
    cp_s(sm + E_B2, B2, 64, tid, 256);
    cp_s(sm + E_CB1, Cb1, 64, tid, 256);
    cp_s(sm + E_C2, C2, 64, tid, 256);
    cp_s(sm + E_W129, W1 + 8192, 64, tid, 256);
    if (tid == 0) sm[E_CB2] = Cb2[0];
    __syncthreads();

    const int lane = tid & 31;
    const int wid = tid >> 5;
    const int g = lane >> 2;
    const int q = lane & 3;
    uint32_t *m1s = smu + E_WARP + wid * E_WARP_WORDS;
    float *cwbuf = sm + E_WARP + wid * E_WARP_WORDS + 2176;

    const float *ga = (const float *)g_a4;
    const float *gb = (const float *)g_b4;
    float *gagg = (float *)g_agg4;

    const float w129x = sm[E_W129 + 2 * lane];
    const float w129y = sm[E_W129 + 2 * lane + 1];
    const float cb2v = sm[E_CB2];

    int gwarp = blockIdx.x * 8 + wid;
    int nwarps = gridDim.x * 8;

    for (int eb = gwarp * 32; eb < NE; eb += nwarps * 32) {
        int e = eb + lane;
        int s = ei[e];
        int d = ei[NE + e];
        float ax = xin[3 * d + 0] - xin[3 * s + 0];
        float ay = xin[3 * d + 1] - xin[3 * s + 1];
        float az = xin[3 * d + 2] - xin[3 * s + 2];
        float d2 = ax * ax + ay * ay + az * az;

        // m1 = silu(a[d] + b[s] + d2*w129)
#pragma unroll
        for (int t = 0; t < 32; t++) {
            int dt = __shfl_sync(0xffffffffu, d, t);
            int st = __shfl_sync(0xffffffffu, s, t);
            float d2t = __shfl_sync(0xffffffffu, d2, t);
            float2 av = *(const float2 *)(ga + (size_t)dt * HH + 2 * lane);
            float2 bv = *(const float2 *)(gb + (size_t)st * HH + 2 * lane);
            float m0 = siluf(fmaf(d2t, w129x, av.x + bv.x));
            float m1v = siluf(fmaf(d2t, w129y, av.y + bv.y));
            uint2 pk;
            pk.x = to_tf32(m0);
            pk.y = to_tf32(m1v);
            *(uint2 *)(m1s + t * 68 + 2 * lane) = pk;
        }
        __syncwarp();

        // GEMM2: m = silu(m1 @ W2 + b2)
        float acc[2][8][4];
        zacc(acc);
        gemmF<8>(acc, m1s, smu + E_W2T, g, q);
        __syncwarp();

#pragma unroll
        for (int m = 0; m < 2; m++) {
            int r0 = 16 * m + g;
            int r1 = r0 + 8;
#pragma unroll
            for (int n = 0; n < 8; n++) {
                int c0 = 8 * n + 2 * q;
                float2 bb = *(const float2 *)(sm + E_B2 + c0);
                uint2 p0, p1;
                p0.x = to_tf32(siluf(acc[m][n][0] + bb.x));
                p0.y = to_tf32(siluf(acc[m][n][1] + bb.y));
                p1.x = to_tf32(siluf(acc[m][n][2] + bb.x));
                p1.y = to_tf32(siluf(acc[m][n][3] + bb.y));
                *(uint2 *)(m1s + r0 * 68 + c0) = p0;
                *(uint2 *)(m1s + r1 * 68 + c0) = p1;
                acc[m][n][0] = 0.f; acc[m][n][1] = 0.f;
                acc[m][n][2] = 0.f; acc[m][n][3] = 0.f;
            }
        }
        __syncwarp();

        // agg scatter: row-coalesced red4 (2 rows / iter)
#pragma unroll
        for (int tt = 0; tt < 32; tt += 2) {
            int row = tt + (lane >> 4);
            int q4 = lane & 15;
            int dt = __shfl_sync(0xffffffffu, d, row);
            const float *mp = (const float *)m1s + row * 68 + 4 * q4;
            float4 v = *(const float4 *)mp;
            red4(gagg + (size_t)dt * HH + 4 * q4, v.x, v.y, v.z, v.w);
        }

        // coord MLP
        gemmF<8>(acc, m1s, smu + E_C1T, g, q);

        float cwp[2][2] = {{0.f, 0.f}, {0.f, 0.f}};
#pragma unroll
        for (int m = 0; m < 2; m++)
#pragma unroll
            for (int n = 0; n < 8; n++) {
                int c0 = 8 * n + 2 * q;
                float2 cb1v = *(const float2 *)(sm + E_CB1 + c0);
                float2 c2v = *(const float2 *)(sm + E_C2 + c0);
                cwp[m][0] += siluf(acc[m][n][0] + cb1v.x) * c2v.x +
                             siluf(acc[m][n][1] + cb1v.y) * c2v.y;
                cwp[m][1] += siluf(acc[m][n][2] + cb1v.x) * c2v.x +
                             siluf(acc[m][n][3] + cb1v.y) * c2v.y;
            }
#pragma unroll
        for (int ofs = 1; ofs <= 2; ofs <<= 1) {
#pragma unroll
            for (int m = 0; m < 2; m++) {
                cwp[m][0] += __shfl_xor_sync(0xffffffffu, cwp[m][0], ofs);
                cwp[m][1] += __shfl_xor_sync(0xffffffffu, cwp[m][1], ofs);
            }
        }
        if (q == 0) {
#pragma unroll
            for (int m = 0; m < 2; m++) {
                cwbuf[16 * m + g] = cwp[m][0] + cb2v;
                cwbuf[16 * m + g + 8] = cwp[m][1] + cb2v;
            }
        }
        __syncwarp();

        float cw = cwbuf[lane];
        red1(&g_dx[3 * d + 0], ax * cw);
        red1(&g_dx[3 * d + 1], ay * cw);
        red1(&g_dx[3 * d + 2], az * cw);
        __syncwarp();
    }
}

// ---------------- node kernel (tensor core, fused next-layer pre) ----------------
#define ND_W1T 0
#define ND_W2T 8448
#define ND_AT 12800
#define ND_BT 17152
#define ND_NB1 21504
#define ND_NB2 21568
#define ND_EB1 21632
#define ND_WARP 21696
#define ND_WARP_WORDS 4224
#define NODE_SMEM_WORDS (ND_WARP + 8 * ND_WARP_WORDS)
#define NODE_SMEM_BYTES (NODE_SMEM_WORDS * 4)

__global__ void __launch_bounds__(256, 1)
node_kernel(float *__restrict__ xout, const float *__restrict__ NW1,
            const float *__restrict__ NB1, const float *__restrict__ NW2,
            const float *__restrict__ NB2, const float *__restrict__ EW1n,
            const float *__restrict__ EB1n, int do_pre) {
    extern __shared__ float sm[];
    uint32_t *smu = (uint32_t *)sm;
    int tid = threadIdx.x;

    for (int idx = tid; idx < 8192; idx += 256) {
        int kk = idx >> 6, nn = idx & 63;
        smu[ND_W1T + nn * 132 + kk] = to_tf32(NW1[kk * 64 + nn]);
    }
    for (int idx = tid; idx < 4096; idx += 256) {
        int kk = idx >> 6, nn = idx & 63;
        smu[ND_W2T + nn * 68 + kk] = to_tf32(NW2[idx]);
        if (do_pre) {
            smu[ND_AT + nn * 68 + kk] = to_tf32(EW1n[kk * 64 + nn]);
            smu[ND_BT + nn * 68 + kk] = to_tf32(EW1n[(64 + kk) * 64 + nn]);
        }
    }
    cp_s(sm + ND_NB1, NB1, 64, tid, 256);
    cp_s(sm + ND_NB2, NB2, 64, tid, 256);
    if (do_pre) cp_s(sm + ND_EB1, EB1n, 64, tid, 256);
    __syncthreads();

    const int lane = tid & 31, wid = tid >> 5;
    const int g = lane >> 2, q = lane & 3;
    uint32_t *buf = smu + ND_WARP + wid * ND_WARP_WORDS;

    float *gh = (float *)g_h4;
    float *gagg = (float *)g_agg4;
    float *gaA = (float *)g_a4;
    float *gaB = (float *)g_b4;

    int gwarp = blockIdx.x * 8 + wid;
    int nwarps = gridDim.x * 8;

    for (int i0 = gwarp * 32; i0 < NN; i0 += nwarps * 32) {
        // stage nf = [h, agg] as tf32 (stride 132); zero agg
#pragma unroll
        for (int t = 0; t < 32; t++) {
            size_t ro = (size_t)(i0 + t) * HH;
            float2 hv = *(const float2 *)(gh + ro + 2 * lane);
            float2 av = *(const float2 *)(gagg + ro + 2 * lane);
            *(float2 *)(gagg + ro + 2 * lane) = make_float2(0.f, 0.f);
            uint2 ph, pa;
            ph.x = to_tf32(hv.x); ph.y = to_tf32(hv.y);
            pa.x = to_tf32(av.x); pa.y = to_tf32(av.y);
            *(uint2 *)(buf + t * 132 + 2 * lane) = ph;
            *(uint2 *)(buf + t * 132 + 64 + 2 * lane) = pa;
        }
        __syncwarp();

        float acc[2][8][4];
        zacc(acc);
        gemmT<132, 132, 16>(acc, buf, smu + ND_W1T, g, q);
        __syncwarp();

        // m1 = silu(acc + nb1) -> restage stride 68
#pragma unroll
        for (int m = 0; m < 2; m++) {
            int r0 = 16 * m + g, r1 = r0 + 8;
#pragma unroll
            for (int n = 0; n < 8; n++) {
                int c0 = 8 * n + 2 * q;
                float2 bb = *(const float2 *)(sm + ND_NB1 + c0);
                uint2 p0, p1;
                p0.x = to_tf32(siluf(acc[m][n][0] + bb.x));
                p0.y = to_tf32(siluf(acc[m][n][1] + bb.y));
                p1.x = to_tf32(siluf(acc[m][n][2] + bb.x));
                p1.y = to_tf32(siluf(acc[m][n][3] + bb.y));
                *(uint2 *)(buf + r0 * 68 + c0) = p0;
                *(uint2 *)(buf + r1 * 68 + c0) = p1;
            }
        }
        __syncwarp();

        zacc(acc);
        gemmT<68, 68, 8>(acc, buf, smu + ND_W2T, g, q);
        __syncwarp();

        // hnew = h_old + acc + nb2 -> global h, restage tf32 for pre gemms
#pragma unroll
        for (int m = 0; m < 2; m++) {
            int r0 = 16 * m + g, r1 = r0 + 8;
            float *h0 = gh + (size_t)(i0 + r0) * HH;
            float *h1 = gh + (size_t)(i0 + r1) * HH;
#pragma unroll
            for (int n = 0; n < 8; n++) {
                int c0 = 8 * n + 2 * q;
                float2 bb = *(const float2 *)(sm + ND_NB2 + c0);
                float2 o0 = *(const float2 *)(h0 + c0);
                float2 o1 = *(const float2 *)(h1 + c0);
                o0.x += acc[m][n][0] + bb.x;
                o0.y += acc[m][n][1] + bb.y;
                o1.x += acc[m][n][2] + bb.x;
                o1.y += acc[m][n][3] + bb.y;
                *(float2 *)(h0 + c0) = o0;
                *(float2 *)(h1 + c0) = o1;
                if (do_pre) {
                    uint2 p0, p1;
                    p0.x = to_tf32(o0.x); p0.y = to_tf32(o0.y);
                    p1.x = to_tf32(o1.x); p1.y = to_tf32(o1.y);
                    *(uint2 *)(buf + r0 * 68 + c0) = p0;
                    *(uint2 *)(buf + r1 * 68 + c0) = p1;
                }
            }
        }
        __syncwarp();

        if (do_pre) {
            zacc(acc);
            gemmT<68, 68, 8>(acc, buf, smu + ND_AT, g, q);
#pragma unroll
            for (int m = 0; m < 2; m++) {
                int r0 = 16 * m + g, r1 = r0 + 8;
#pragma unroll
                for (int n = 0; n < 8; n++) {
                    int c0 = 8 * n + 2 * q;
                    float2 bb = *(const float2 *)(sm + ND_EB1 + c0);
                    float2 v0 = {acc[m][n][0] + bb.x, acc[m][n][1] + bb.y};
                    float2 v1 = {acc[m][n][2] + bb.x, acc[m][n][3] + bb.y};
                    *(float2 *)(gaA + (size_t)(i0 + r0) * HH + c0) = v0;
                    *(float2 *)(gaA + (size_t)(i0 + r1) * HH + c0) = v1;
                }
            }
            zacc(acc);
            gemmT<68, 68, 8>(acc, buf, smu + ND_BT, g, q);
#pragma unroll
            for (int m = 0; m < 2; m++) {
                int r0 = 16 * m + g, r1 = r0 + 8;
#pragma unroll
                for (int n = 0; n < 8; n++) {
                    int c0 = 8 * n + 2 * q;
                    float2 v0 = {acc[m][n][0], acc[m][n][1]};
                    float2 v1 = {acc[m][n][2], acc[m][n][3]};
                    *(float2 *)(gaB + (size_t)(i0 + r0) * HH + c0) = v0;
                    *(float2 *)(gaB + (size_t)(i0 + r1) * HH + c0) = v1;
                }
            }
        }

        // x += dx; reset dx (lane = node)
        int i = i0 + lane;
#pragma unroll
        for (int k = 0; k < 3; k++) {
            xout[3 * i + k] += g_dx[3 * i + k];
            g_dx[3 * i + k] = 0.f;
        }
        __syncwarp();
    }
}

// ---------------- launch ----------------
extern "C" void kernel_launch(void *const *d_in, const int *in_sizes, int n_in,
                              void *d_out, int out_size) {
    const float *x   = (const float *)d_in[0];
    const int   *z   = (const int *)d_in[1];
    const float *t   = (const float *)d_in[2];
    const int   *ei  = (const int *)d_in[3];
    const float *emb = (const float *)d_in[4];
    const float *tw1 = (const float *)d_in[5];
    const float *tb1 = (const float *)d_in[6];
    const float *tw2 = (const float *)d_in[7];
    const float *tb2 = (const float *)d_in[8];
    const float *ew1 = (const float *)d_in[9];
    const float *eb1 = (const float *)d_in[10];
    const float *ew2 = (const float *)d_in[11];
    const float *eb2 = (const float *)d_in[12];
    const float *cw1 = (const float *)d_in[13];
    const float *cb1 = (const float *)d_in[14];
    const float *cw2 = (const float *)d_in[15];
    const float *cb2 = (const float *)d_in[16];
    const float *nw1 = (const float *)d_in[17];
    const float *nb1 = (const float *)d_in[18];
    const float *nw2 = (const float *)d_in[19];
    const float *nb2 = (const float *)d_in[20];
    float *out = (float *)d_out;

    cudaFuncSetAttribute(edge_kernel, cudaFuncAttributeMaxDynamicSharedMemorySize,
                         EDGE_SMEM_BYTES);
    cudaFuncSetAttribute(node_kernel, cudaFuncAttributeMaxDynamicSharedMemorySize,
                         NODE_SMEM_BYTES);
    cudaFuncSetAttribute(pre0_kernel, cudaFuncAttributeMaxDynamicSharedMemorySize,
                         PRE_SMEM_BYTES);

    tmean_kernel<<<1, 64>>>(t, tw1, tb1, tw2, tb2);
    init_kernel<<<2048, 256>>>(x, z, emb, out);
    pre0_kernel<<<296, 256, PRE_SMEM_BYTES>>>(ew1, eb1);
    for (int l = 0; l < NLAYERS; l++) {
        edge_kernel<<<296, 256, EDGE_SMEM_BYTES>>>(
            out, ei, ew1 + l * 8256, ew2 + l * 4096, eb2 + l * 64,
            cw1 + l * 4096, cb1 + l * 64, cw2 + l * 64, cb2 + l);
        int do_pre = (l + 1 < NLAYERS);
        node_kernel<<<148, 256, NODE_SMEM_BYTES>>>(
            out, nw1 + l * 8192, nb1 + l * 64, nw2 + l * 4096, nb2 + l * 64,
            do_pre ? (ew1 + (l + 1) * 8256) : ew1,
            do_pre ? (eb1 + (l + 1) * 64) : eb1, do_pre);
    }
    (void)in_sizes; (void)n_in; (void)out_size;
}

// round 7
// speedup vs baseline: 6.9315x; 1.2119x over previous
#include <cuda_runtime.h>
#include <cuda_fp16.h>
#include <cstdint>

#define NN 100000
#define NE 1600000
#define HH 64
#define NLAYERS 3

// ---------------- device scratch ----------------
__device__ float4 g_h4[NN * 16];     // h: (N, 64) fp32
__device__ float4 g_agg4[NN * 16];   // agg: (N, 64) fp32
__device__ __half2 g_ah[NN * 32];    // a[n] = h[n] @ W1[0:64] + e_b1 (fp16)
__device__ __half2 g_bh[NN * 32];    // b[n] = h[n] @ W1[64:128]      (fp16)
__device__ float  g_dx[NN * 3];
__device__ float4 g_tmean4[16];

// ---------------- helpers ----------------
__device__ __forceinline__ float siluf(float v) {
    float th;
    float hv = 0.5f * v;
    asm("tanh.approx.f32 %0, %1;" : "=f"(th) : "f"(hv));
    return fmaf(hv, th, hv);
}
__device__ __forceinline__ float silux(float v) {
    return __fdividef(v, 1.0f + __expf(-v));
}
__device__ __forceinline__ void red2(float *p, float a, float b) {
    asm volatile("red.global.add.v2.f32 [%0], {%1,%2};" ::"l"(p), "f"(a), "f"(b)
                 : "memory");
}
__device__ __forceinline__ void red1(float *p, float a) {
    asm volatile("red.global.add.f32 [%0], %1;" ::"l"(p), "f"(a) : "memory");
}
__device__ __forceinline__ uint32_t h2u(__half2 h) {
    return *reinterpret_cast<uint32_t *>(&h);
}
__device__ __forceinline__ uint32_t packh(float a, float b) {
    __half2 h = __floats2half2_rn(a, b);
    return h2u(h);
}
// pair-slot index for fp16x2 word w (= k/2) within a row
__device__ __forceinline__ int pslot(int w) {
    return 8 * (w >> 3) + 2 * (w & 3) + ((w >> 2) & 1);
}
__device__ __forceinline__ void mma_f16(float (&d)[4], uint32_t a0, uint32_t a1,
                                        uint32_t a2, uint32_t a3, uint32_t b0,
                                        uint32_t b1) {
    asm volatile(
        "mma.sync.aligned.m16n8k16.row.col.f32.f16.f16.f32 "
        "{%0,%1,%2,%3}, {%4,%5,%6,%7}, {%8,%9}, {%0,%1,%2,%3};\n"
        : "+f"(d[0]), "+f"(d[1]), "+f"(d[2]), "+f"(d[3])
        : "r"(a0), "r"(a1), "r"(a2), "r"(a3), "r"(b0), "r"(b1));
}

// 32 x (16*KS16) A (fp16x2 pair-slot rows, stride SA words) @ B (fp16x2
// pair-slot [n][k], stride SB). acc layout: rows 16m+g / +8, cols 8n+2q..+1.
template <int SA, int SB, int KS16>
__device__ __forceinline__ void gemmH(float (&acc)[2][8][4],
                                      const uint32_t *__restrict__ A,
                                      const uint32_t *__restrict__ B, int g,
                                      int q) {
#pragma unroll
    for (int ks = 0; ks < KS16; ks++) {
        uint2 bf[8];
#pragma unroll
        for (int n = 0; n < 8; n++)
            bf[n] = *(const uint2 *)(B + (8 * n + g) * SB + 8 * ks + 2 * q);
#pragma unroll
        for (int m = 0; m < 2; m++) {
            const uint32_t *ap = A + (16 * m + g) * SA + 8 * ks + 2 * q;
            uint2 lo = *(const uint2 *)ap;            // row g: (a0, a2)
            uint2 hi = *(const uint2 *)(ap + 8 * SA); // row g+8: (a1, a3)
#pragma unroll
            for (int n = 0; n < 8; n++)
                mma_f16(acc[m][n], lo.x, hi.x, lo.y, hi.y, bf[n].x, bf[n].y);
        }
    }
}
__device__ __forceinline__ void zacc(float (&acc)[2][8][4]) {
#pragma unroll
    for (int m = 0; m < 2; m++)
#pragma unroll
        for (int n = 0; n < 8; n++)
#pragma unroll
            for (int v = 0; v < 4; v++) acc[m][n][v] = 0.f;
}
__device__ __forceinline__ void cp_s(float *dst, const float *__restrict__ src,
                                     int nfloats, int tid, int nthr) {
    const float4 *s4 = (const float4 *)src;
    float4 *d4 = (float4 *)dst;
    for (int k = tid; k < (nfloats >> 2); k += nthr) d4[k] = s4[k];
}

// stage K x 64 row-major fp32 weights into fp16x2 pair-slot [64][stride]
__device__ __forceinline__ void stage_w16(uint32_t *dst, const float *__restrict__ W,
                                          int kwords, int stride, int tid,
                                          int nthr) {
    for (int idx = tid; idx < 64 * kwords; idx += nthr) {
        int n = idx / kwords, w = idx % kwords;
        dst[n * stride + pslot(w)] =
            packh(W[(2 * w) * 64 + n], W[(2 * w + 1) * 64 + n]);
    }
}

// ---------------- time-embedding mean ----------------
__global__ void tmean_kernel(const float *__restrict__ t,
                             const float *__restrict__ w1,
                             const float *__restrict__ b1,
                             const float *__restrict__ w2,
                             const float *__restrict__ b2) {
    __shared__ float sS[16 * 64];
    int j = threadIdx.x;
    float w1j = w1[j], b1j = b1[j];
    for (int b = 0; b < 16; b++) sS[b * 64 + j] = silux(t[b] * w1j + b1j);
    __syncthreads();
    float accm = 0.f;
    for (int b = 0; b < 16; b++) {
        float s = b2[j];
        for (int k = 0; k < 64; k++) s += sS[b * 64 + k] * w2[k * 64 + j];
        accm += s;
    }
    ((float *)g_tmean4)[j] = accm * (1.0f / 16.0f);
}

// ---------------- init ----------------
__global__ void init_kernel(const float *__restrict__ x, const int *__restrict__ z,
                            const float *__restrict__ emb, float *__restrict__ out) {
    int tid = blockIdx.x * blockDim.x + threadIdx.x;
    int stride = gridDim.x * blockDim.x;
    const float4 *emb4 = (const float4 *)emb;
    for (int idx = tid; idx < NN * 16; idx += stride) {
        int i = idx >> 4, qq = idx & 15;
        float4 e = emb4[z[i] * 16 + qq];
        float4 tm = g_tmean4[qq];
        float4 r;
        r.x = e.x + tm.x; r.y = e.y + tm.y; r.z = e.z + tm.z; r.w = e.w + tm.w;
        g_h4[idx] = r;
        g_agg4[idx] = make_float4(0.f, 0.f, 0.f, 0.f);
    }
    for (int idx = tid; idx < NN * 3; idx += stride) {
        out[idx] = x[idx];
        g_dx[idx] = 0.f;
    }
}

// ---------------- pre0: a,b for layer 0 (fp16 tensor core) ----------------
#define PR_AT 0
#define PR_BT 2560
#define PR_EB1 5120
#define PR_WARP 5184
#define PR_WARP_WORDS 1280
#define PRE_SMEM_BYTES ((PR_WARP + 8 * PR_WARP_WORDS) * 4)

__global__ void __launch_bounds__(256, 2)
pre0_kernel(const float *__restrict__ W1, const float *__restrict__ B1) {
    extern __shared__ float sm[];
    uint32_t *smu = (uint32_t *)sm;
    int tid = threadIdx.x;
    stage_w16(smu + PR_AT, W1, 32, 40, tid, 256);
    stage_w16(smu + PR_BT, W1 + 64 * 64, 32, 40, tid, 256);
    cp_s(sm + PR_EB1, B1, 64, tid, 256);
    __syncthreads();

    const int lane = tid & 31, wid = tid >> 5;
    const int g = lane >> 2, q = lane & 3;
    uint32_t *buf = smu + PR_WARP + wid * PR_WARP_WORDS;
    const float *gh = (const float *)g_h4;
    const int sl = pslot(lane);

    int gwarp = blockIdx.x * 8 + wid;
    int nwarps = gridDim.x * 8;
    for (int i0 = gwarp * 32; i0 < NN; i0 += nwarps * 32) {
#pragma unroll
        for (int t = 0; t < 32; t++) {
            float2 hv = *(const float2 *)(gh + (size_t)(i0 + t) * HH + 2 * lane);
            buf[t * 40 + sl] = packh(hv.x, hv.y);
        }
        __syncwarp();
        float acc[2][8][4];
        zacc(acc);
        gemmH<40, 40, 4>(acc, buf, smu + PR_AT, g, q);
#pragma unroll
        for (int m = 0; m < 2; m++) {
            int r0 = 16 * m + g, r1 = r0 + 8;
#pragma unroll
            for (int n = 0; n < 8; n++) {
                int w = 4 * n + q;
                float2 bb = *(const float2 *)(sm + PR_EB1 + 2 * w);
                g_ah[(size_t)(i0 + r0) * 32 + w] =
                    __floats2half2_rn(acc[m][n][0] + bb.x, acc[m][n][1] + bb.y);
                g_ah[(size_t)(i0 + r1) * 32 + w] =
                    __floats2half2_rn(acc[m][n][2] + bb.x, acc[m][n][3] + bb.y);
            }
        }
        zacc(acc);
        gemmH<40, 40, 4>(acc, buf, smu + PR_BT, g, q);
#pragma unroll
        for (int m = 0; m < 2; m++) {
            int r0 = 16 * m + g, r1 = r0 + 8;
#pragma unroll
            for (int n = 0; n < 8; n++) {
                int w = 4 * n + q;
                g_bh[(size_t)(i0 + r0) * 32 + w] =
                    __floats2half2_rn(acc[m][n][0], acc[m][n][1]);
                g_bh[(size_t)(i0 + r1) * 32 + w] =
                    __floats2half2_rn(acc[m][n][2], acc[m][n][3]);
            }
        }
        __syncwarp();
    }
}

// ---------------- edge kernel (fp16 tensor core) ----------------
#define E_W2T 0
#define E_C1T 2560
#define E_B2 5120
#define E_CB1 5184
#define E_C2 5248
#define E_W129 5312
#define E_CB2 5376
#define E_WARP 5384
#define E_WARP_WORDS 1312   /* m1s 32*40 + cwbuf 32 */
#define EDGE_SMEM_BYTES ((E_WARP + 8 * E_WARP_WORDS) * 4)

__global__ void __launch_bounds__(256, 2)
edge_kernel(const float *__restrict__ xin, const int *__restrict__ ei,
            const float *__restrict__ W1, const float *__restrict__ W2,
            const float *__restrict__ B2, const float *__restrict__ C1,
            const float *__restrict__ Cb1, const float *__restrict__ C2,
            const float *__restrict__ Cb2) {
    extern __shared__ float sm[];
    uint32_t *smu = (uint32_t *)sm;
    int tid = threadIdx.x;

    stage_w16(smu + E_W2T, W2, 32, 40, tid, 256);
    stage_w16(smu + E_C1T, C1, 32, 40, tid, 256);
    cp_s(sm + E_B2, B2, 64, tid, 256);
    cp_s(sm + E_CB1, Cb1, 64, tid, 256);
    cp_s(sm + E_C2, C2, 64, tid, 256);
    cp_s(sm + E_W129, W1 + 8192, 64, tid, 256);
    if (tid == 0) sm[E_CB2] = Cb2[0];
    __syncthreads();

    const int lane = tid & 31;
    const int wid = tid >> 5;
    const int g = lane >> 2;
    const int q = lane & 3;
    uint32_t *m1s = smu + E_WARP + wid * E_WARP_WORDS;
    float *cwbuf = sm + E_WARP + wid * E_WARP_WORDS + 1280;
    const int sl = pslot(lane);

    float *gagg = (float *)g_agg4;

    const float w129x = sm[E_W129 + 2 * lane];
    const float w129y = sm[E_W129 + 2 * lane + 1];
    const float cb2v = sm[E_CB2];

    int gwarp = blockIdx.x * 8 + wid;
    int nwarps = gridDim.x * 8;

    for (int eb = gwarp * 32; eb < NE; eb += nwarps * 32) {
        int e = eb + lane;
        int s = ei[e];
        int d = ei[NE + e];
        float ax = xin[3 * d + 0] - xin[3 * s + 0];
        float ay = xin[3 * d + 1] - xin[3 * s + 1];
        float az = xin[3 * d + 2] - xin[3 * s + 2];
        float d2 = ax * ax + ay * ay + az * az;

        // m1 = silu(a[d] + b[s] + d2*w129) -> staged fp16 pair-slot
#pragma unroll
        for (int t = 0; t < 32; t++) {
            int dt = __shfl_sync(0xffffffffu, d, t);
            int st = __shfl_sync(0xffffffffu, s, t);
            float d2t = __shfl_sync(0xffffffffu, d2, t);
            float2 av = __half22float2(g_ah[(size_t)dt * 32 + lane]);
            float2 bv = __half22float2(g_bh[(size_t)st * 32 + lane]);
            float m0 = siluf(fmaf(d2t, w129x, av.x + bv.x));
            float m1v = siluf(fmaf(d2t, w129y, av.y + bv.y));
            m1s[t * 40 + sl] = packh(m0, m1v);
        }
        __syncwarp();

        // GEMM2: m = silu(m1 @ W2 + b2)
        float acc[2][8][4];
        zacc(acc);
        gemmH<40, 40, 4>(acc, m1s, smu + E_W2T, g, q);
        __syncwarp();

        // epilogue: silu, register-direct red2 agg scatter, restage m fp16
#pragma unroll
        for (int m = 0; m < 2; m++) {
            int r0 = 16 * m + g;
            int r1 = r0 + 8;
            int d0 = __shfl_sync(0xffffffffu, d, r0);
            int d1 = __shfl_sync(0xffffffffu, d, r1);
            float *agg0 = gagg + (size_t)d0 * HH;
            float *agg1 = gagg + (size_t)d1 * HH;
#pragma unroll
            for (int n = 0; n < 8; n++) {
                int c0 = 8 * n + 2 * q;
                float2 bb = *(const float2 *)(sm + E_B2 + c0);
                float v00 = siluf(acc[m][n][0] + bb.x);
                float v01 = siluf(acc[m][n][1] + bb.y);
                float v10 = siluf(acc[m][n][2] + bb.x);
                float v11 = siluf(acc[m][n][3] + bb.y);
                red2(agg0 + c0, v00, v01);
                red2(agg1 + c0, v10, v11);
                int slw = 8 * (n >> 1) + 2 * q + (n & 1);
                m1s[r0 * 40 + slw] = packh(v00, v01);
                m1s[r1 * 40 + slw] = packh(v10, v11);
                acc[m][n][0] = 0.f; acc[m][n][1] = 0.f;
                acc[m][n][2] = 0.f; acc[m][n][3] = 0.f;
            }
        }
        __syncwarp();

        // coord MLP: cw = silu(m @ C1 + cb1) @ C2 + cb2
        gemmH<40, 40, 4>(acc, m1s, smu + E_C1T, g, q);

        float cwp[2][2] = {{0.f, 0.f}, {0.f, 0.f}};
#pragma unroll
        for (int m = 0; m < 2; m++)
#pragma unroll
            for (int n = 0; n < 8; n++) {
                int c0 = 8 * n + 2 * q;
                float2 cb1v = *(const float2 *)(sm + E_CB1 + c0);
                float2 c2v = *(const float2 *)(sm + E_C2 + c0);
                cwp[m][0] += siluf(acc[m][n][0] + cb1v.x) * c2v.x +
                             siluf(acc[m][n][1] + cb1v.y) * c2v.y;
                cwp[m][1] += siluf(acc[m][n][2] + cb1v.x) * c2v.x +
                             siluf(acc[m][n][3] + cb1v.y) * c2v.y;
            }
#pragma unroll
        for (int ofs = 1; ofs <= 2; ofs <<= 1) {
#pragma unroll
            for (int m = 0; m < 2; m++) {
                cwp[m][0] += __shfl_xor_sync(0xffffffffu, cwp[m][0], ofs);
                cwp[m][1] += __shfl_xor_sync(0xffffffffu, cwp[m][1], ofs);
            }
        }
        if (q == 0) {
#pragma unroll
            for (int m = 0; m < 2; m++) {
                cwbuf[16 * m + g] = cwp[m][0] + cb2v;
                cwbuf[16 * m + g + 8] = cwp[m][1] + cb2v;
            }
        }
        __syncwarp();

        float cw = cwbuf[lane];
        red1(&g_dx[3 * d + 0], ax * cw);
        red1(&g_dx[3 * d + 1], ay * cw);
        red1(&g_dx[3 * d + 2], az * cw);
        __syncwarp();
    }
}

// ---------------- node kernel (fp16 tensor core, fused next-layer pre) -----
#define ND_W1T 0
#define ND_W2T 4608
#define ND_AT 7168
#define ND_BT 9728
#define ND_NB1 12288
#define ND_NB2 12352
#define ND_EB1 12416
#define ND_WARP 12480
#define ND_WARP_WORDS 2304
#define NODE_SMEM_BYTES ((ND_WARP + 8 * ND_WARP_WORDS) * 4)

__global__ void __launch_bounds__(256, 1)
node_kernel(float *__restrict__ xout, const float *__restrict__ NW1,
            const float *__restrict__ NB1, const float *__restrict__ NW2,
            const float *__restrict__ NB2, const float *__restrict__ EW1n,
            const float *__restrict__ EB1n, int do_pre) {
    extern __shared__ float sm[];
    uint32_t *smu = (uint32_t *)sm;
    int tid = threadIdx.x;

    stage_w16(smu + ND_W1T, NW1, 64, 72, tid, 256);
    stage_w16(smu + ND_W2T, NW2, 32, 40, tid, 256);
    if (do_pre) {
        stage_w16(smu + ND_AT, EW1n, 32, 40, tid, 256);
        stage_w16(smu + ND_BT, EW1n + 64 * 64, 32, 40, tid, 256);
    }
    cp_s(sm + ND_NB1, NB1, 64, tid, 256);
    cp_s(sm + ND_NB2, NB2, 64, tid, 256);
    if (do_pre) cp_s(sm + ND_EB1, EB1n, 64, tid, 256);
    __syncthreads();

    const int lane = tid & 31, wid = tid >> 5;
    const int g = lane >> 2, q = lane & 3;
    uint32_t *buf = smu + ND_WARP + wid * ND_WARP_WORDS;
    const int sl = pslot(lane);

    float *gh = (float *)g_h4;
    float *gagg = (float *)g_agg4;

    int gwarp = blockIdx.x * 8 + wid;
    int nwarps = gridDim.x * 8;

    for (int i0 = gwarp * 32; i0 < NN; i0 += nwarps * 32) {
        // stage nf = [h, agg] fp16 (stride 72); zero agg
#pragma unroll
        for (int t = 0; t < 32; t++) {
            size_t ro = (size_t)(i0 + t) * HH;
            float2 hv = *(const float2 *)(gh + ro + 2 * lane);
            float2 av = *(const float2 *)(gagg + ro + 2 * lane);
            *(float2 *)(gagg + ro + 2 * lane) = make_float2(0.f, 0.f);
            buf[t * 72 + sl] = packh(hv.x, hv.y);
            buf[t * 72 + 32 + sl] = packh(av.x, av.y);
        }
        __syncwarp();

        float acc[2][8][4];
        zacc(acc);
        gemmH<72, 72, 8>(acc, buf, smu + ND_W1T, g, q);
        __syncwarp();

        // m1 = silu(acc + nb1) -> restage fp16 stride 40
#pragma unroll
        for (int m = 0; m < 2; m++) {
            int r0 = 16 * m + g, r1 = r0 + 8;
#pragma unroll
            for (int n = 0; n < 8; n++) {
                int c0 = 8 * n + 2 * q;
                float2 bb = *(const float2 *)(sm + ND_NB1 + c0);
                int slw = 8 * (n >> 1) + 2 * q + (n & 1);
                buf[r0 * 40 + slw] = packh(siluf(acc[m][n][0] + bb.x),
                                           siluf(acc[m][n][1] + bb.y));
                buf[r1 * 40 + slw] = packh(siluf(acc[m][n][2] + bb.x),
                                           siluf(acc[m][n][3] + bb.y));
            }
        }
        __syncwarp();

        zacc(acc);
        gemmH<40, 40, 4>(acc, buf, smu + ND_W2T, g, q);
        __syncwarp();

        // hnew = h_old + acc + nb2 -> global; restage hnew fp16 for pre
#pragma unroll
        for (int m = 0; m < 2; m++) {
            int r0 = 16 * m + g, r1 = r0 + 8;
            float *h0 = gh + (size_t)(i0 + r0) * HH;
            float *h1 = gh + (size_t)(i0 + r1) * HH;
#pragma unroll
            for (int n = 0; n < 8; n++) {
                int c0 = 8 * n + 2 * q;
                float2 bb = *(const float2 *)(sm + ND_NB2 + c0);
                float2 o0 = *(const float2 *)(h0 + c0);
                float2 o1 = *(const float2 *)(h1 + c0);
                o0.x += acc[m][n][0] + bb.x;
                o0.y += acc[m][n][1] + bb.y;
                o1.x += acc[m][n][2] + bb.x;
                o1.y += acc[m][n][3] + bb.y;
                *(float2 *)(h0 + c0) = o0;
                *(float2 *)(h1 + c0) = o1;
                if (do_pre) {
                    int slw = 8 * (n >> 1) + 2 * q + (n & 1);
                    buf[r0 * 40 + slw] = packh(o0.x, o0.y);
                    buf[r1 * 40 + slw] = packh(o1.x, o1.y);
                }
            }
        }
        __syncwarp();

        if (do_pre) {
            zacc(acc);
            gemmH<40, 40, 4>(acc, buf, smu + ND_AT, g, q);
#pragma unroll
            for (int m = 0; m < 2; m++) {
                int r0 = 16 * m + g, r1 = r0 + 8;
#pragma unroll
                for (int n = 0; n < 8; n++) {
                    int w = 4 * n + q;
                    float2 bb = *(const float2 *)(sm + ND_EB1 + 2 * w);
                    g_ah[(size_t)(i0 + r0) * 32 + w] = __floats2half2_rn(
                        acc[m][n][0] + bb.x, acc[m][n][1] + bb.y);
                    g_ah[(size_t)(i0 + r1) * 32 + w] = __floats2half2_rn(
                        acc[m][n][2] + bb.x, acc[m][n][3] + bb.y);
                }
            }
            zacc(acc);
            gemmH<40, 40, 4>(acc, buf, smu + ND_BT, g, q);
#pragma unroll
            for (int m = 0; m < 2; m++) {
                int r0 = 16 * m + g, r1 = r0 + 8;
#pragma unroll
                for (int n = 0; n < 8; n++) {
                    int w = 4 * n + q;
                    g_bh[(size_t)(i0 + r0) * 32 + w] =
                        __floats2half2_rn(acc[m][n][0], acc[m][n][1]);
                    g_bh[(size_t)(i0 + r1) * 32 + w] =
                        __floats2half2_rn(acc[m][n][2], acc[m][n][3]);
                }
            }
        }

        // x += dx; reset dx (lane = node)
        int i = i0 + lane;
#pragma unroll
        for (int k = 0; k < 3; k++) {
            xout[3 * i + k] += g_dx[3 * i + k];
            g_dx[3 * i + k] = 0.f;
        }
        __syncwarp();
    }
}

// ---------------- launch ----------------
extern "C" void kernel_launch(void *const *d_in, const int *in_sizes, int n_in,
                              void *d_out, int out_size) {
    const float *x   = (const float *)d_in[0];
    const int   *z   = (const int *)d_in[1];
    const float *t   = (const float *)d_in[2];
    const int   *ei  = (const int *)d_in[3];
    const float *emb = (const float *)d_in[4];
    const float *tw1 = (const float *)d_in[5];
    const float *tb1 = (const float *)d_in[6];
    const float *tw2 = (const float *)d_in[7];
    const float *tb2 = (const float *)d_in[8];
    const float *ew1 = (const float *)d_in[9];
    const float *eb1 = (const float *)d_in[10];
    const float *ew2 = (const float *)d_in[11];
    const float *eb2 = (const float *)d_in[12];
    const float *cw1 = (const float *)d_in[13];
    const float *cb1 = (const float *)d_in[14];
    const float *cw2 = (const float *)d_in[15];
    const float *cb2 = (const float *)d_in[16];
    const float *nw1 = (const float *)d_in[17];
    const float *nb1 = (const float *)d_in[18];
    const float *nw2 = (const float *)d_in[19];
    const float *nb2 = (const float *)d_in[20];
    float *out = (float *)d_out;

    cudaFuncSetAttribute(edge_kernel, cudaFuncAttributeMaxDynamicSharedMemorySize,
                         EDGE_SMEM_BYTES);
    cudaFuncSetAttribute(node_kernel, cudaFuncAttributeMaxDynamicSharedMemorySize,
                         NODE_SMEM_BYTES);
    cudaFuncSetAttribute(pre0_kernel, cudaFuncAttributeMaxDynamicSharedMemorySize,
                         PRE_SMEM_BYTES);

    tmean_kernel<<<1, 64>>>(t, tw1, tb1, tw2, tb2);
    init_kernel<<<2048, 256>>>(x, z, emb, out);
    pre0_kernel<<<296, 256, PRE_SMEM_BYTES>>>(ew1, eb1);
    for (int l = 0; l < NLAYERS; l++) {
        edge_kernel<<<296, 256, EDGE_SMEM_BYTES>>>(
            out, ei, ew1 + l * 8256, ew2 + l * 4096, eb2 + l * 64,
            cw1 + l * 4096, cb1 + l * 64, cw2 + l * 64, cb2 + l);
        int do_pre = (l + 1 < NLAYERS);
        node_kernel<<<148, 256, NODE_SMEM_BYTES>>>(
            out, nw1 + l * 8192, nb1 + l * 64, nw2 + l * 4096, nb2 + l * 64,
            do_pre ? (ew1 + (l + 1) * 8256) : ew1,
            do_pre ? (eb1 + (l + 1) * 64) : eb1, do_pre);
    }
    (void)in_sizes; (void)n_in; (void)out_size;
}